// round 3
// baseline (speedup 1.0000x reference)
#include <cuda_runtime.h>
#include <cuda.h>
#include <cuda_fp8.h>
#include <cuda_fp16.h>
#include <cuda_bf16.h>
#include <cstdint>
#include <cstdio>

// ============================================================================
// Arch-feature gate: tcgen05 / .cta_group are only legal in PTX modules whose
// virtual arch is arch-specific (compute_103a) or family-specific (compute_103f).
// ============================================================================
#if defined(__CUDA_ARCH__) && \
    (defined(__CUDA_ARCH_FEAT_SM103_ALL) || defined(__CUDA_ARCH_FEAT_SM100_ALL) || \
     defined(__CUDA_ARCH_SPECIFIC__) || defined(__CUDA_ARCH_FAMILY_SPECIFIC__))
#define HAS_TCGEN05 1
#else
#define HAS_TCGEN05 0
#endif

// ============================================================================
// Helpers
// ============================================================================

__device__ __forceinline__ uint32_t elect_one_pred() {
    uint32_t pred;
    asm volatile(
        "{\n\t"
        ".reg .pred p;\n\t"
        "elect.sync _|p, 0xFFFFFFFF;\n\t"
        "selp.b32 %0, 1, 0, p;\n\t"
        "}"
        : "=r"(pred));
    return pred;
}

__device__ __forceinline__ uint32_t smem_to_u32(const void* smem_ptr) {
    uint32_t addr;
    asm("{ .reg .u64 tmp; cvta.to.shared.u64 tmp, %1; cvt.u32.u64 %0, tmp; }"
        : "=r"(addr) : "l"(smem_ptr));
    return addr;
}

#define MBARRIER_INIT(mbar, count) \
    asm volatile("mbarrier.init.shared.b64 [%0], %1;" \
                 :: "r"((uint32_t)(mbar)), "r"((uint32_t)(count)) : "memory")

#define MBARRIER_EXPECT_TX(mbar, tx_bytes) \
    asm volatile("mbarrier.arrive.expect_tx.shared.b64 _, [%0], %1;" \
                 :: "r"((uint32_t)(mbar)), "r"((uint32_t)(tx_bytes)) : "memory")

#define MBARRIER_WAIT_PARITY(mbar, parity) do {                                  \
    uint32_t _mbar = (uint32_t)(mbar);                                           \
    uint32_t _par  = (uint32_t)(parity);                                         \
    asm volatile(                                                                \
        "{\n\t"                                                                  \
        ".reg .pred P1;\n\t"                                                     \
        "WAIT_LOOP_%=:\n\t"                                                      \
        "mbarrier.try_wait.parity.acquire.cta.shared::cta.b64 P1, [%0], %1, 0x989680;\n\t" \
        "@P1 bra.uni WAIT_DONE_%=;\n\t"                                          \
        "bra.uni WAIT_LOOP_%=;\n\t"                                              \
        "WAIT_DONE_%=:\n\t"                                                      \
        "}"                                                                      \
        :: "r"(_mbar), "r"(_par) : "memory");                                    \
} while (0)

#define MBARRIER_WAIT_PARITY_RELAXED(mbar, parity) do {                          \
    uint32_t _mbar = (uint32_t)(mbar);                                           \
    uint32_t _par  = (uint32_t)(parity);                                         \
    asm volatile(                                                                \
        "{\n\t"                                                                  \
        ".reg .pred P1;\n\t"                                                     \
        "WAIT_LOOP_%=:\n\t"                                                      \
        "mbarrier.try_wait.parity.relaxed.cta.shared::cta.b64 P1, [%0], %1, 0x989680;\n\t" \
        "@P1 bra.uni WAIT_DONE_%=;\n\t"                                          \
        "bra.uni WAIT_LOOP_%=;\n\t"                                              \
        "WAIT_DONE_%=:\n\t"                                                      \
        "}"                                                                      \
        :: "r"(_mbar), "r"(_par) : "memory");                                    \
} while (0)

#define TMA_LOAD_3D(smem_addr, tensor_map, cx, cy, cz, mbar) \
    asm volatile( \
        "cp.async.bulk.tensor.3d.shared::cta.global.tile.mbarrier::complete_tx::bytes " \
        "[%0], [%1, {%2, %3, %4}], [%5];" \
        :: "r"((uint32_t)(smem_addr)), "l"(tensor_map), \
           "r"((int32_t)(cx)), "r"((int32_t)(cy)), "r"((int32_t)(cz)), \
           "r"((uint32_t)(mbar)) \
        : "memory")

#define TCGEN05_ALLOC(smem_result_addr, nCols) \
    asm volatile("tcgen05.alloc.cta_group::1.sync.aligned.shared::cta.b32 [%0], %1;" \
                 :: "r"((uint32_t)(smem_result_addr)), "r"((uint32_t)(nCols)) : "memory")

#define TCGEN05_DEALLOC(tmem_addr, nCols) \
    asm volatile("tcgen05.dealloc.cta_group::1.sync.aligned.b32 %0, %1;" \
                 :: "r"(tmem_addr), "r"((uint32_t)(nCols)))

#define TCGEN05_RELINQUISH_ALLOC_PERMIT() \
    asm volatile("tcgen05.relinquish_alloc_permit.cta_group::1.sync.aligned;")

#define TCGEN05_COMMIT(mbar) \
    asm volatile("tcgen05.commit.cta_group::1.mbarrier::arrive::one.shared::cluster.b64 [%0];" \
                 :: "r"((uint32_t)(mbar)) : "memory")

#define TCGEN05_FENCE_AFTER() \
    asm volatile("tcgen05.fence::after_thread_sync;" ::: "memory")

#define TCGEN05_WAIT_LD() \
    asm volatile("tcgen05.wait::ld.sync.aligned;" ::: "memory")

#define TCGEN05_LD_32X32B_X32(r, tmem_addr) \
    asm volatile( \
        "tcgen05.ld.sync.aligned.32x32b.x32.b32 " \
        "{%0, %1, %2, %3, %4, %5, %6, %7, " \
        " %8, %9, %10, %11, %12, %13, %14, %15, " \
        " %16, %17, %18, %19, %20, %21, %22, %23, " \
        " %24, %25, %26, %27, %28, %29, %30, %31}, [%32];" \
        : "=r"((r)[0]),  "=r"((r)[1]),  "=r"((r)[2]),  "=r"((r)[3]), \
          "=r"((r)[4]),  "=r"((r)[5]),  "=r"((r)[6]),  "=r"((r)[7]), \
          "=r"((r)[8]),  "=r"((r)[9]),  "=r"((r)[10]), "=r"((r)[11]), \
          "=r"((r)[12]), "=r"((r)[13]), "=r"((r)[14]), "=r"((r)[15]), \
          "=r"((r)[16]), "=r"((r)[17]), "=r"((r)[18]), "=r"((r)[19]), \
          "=r"((r)[20]), "=r"((r)[21]), "=r"((r)[22]), "=r"((r)[23]), \
          "=r"((r)[24]), "=r"((r)[25]), "=r"((r)[26]), "=r"((r)[27]), \
          "=r"((r)[28]), "=r"((r)[29]), "=r"((r)[30]), "=r"((r)[31]) \
        : "r"(tmem_addr))

// SW128 K-major SMEM descriptor (LBO=1, SBO=64, version=1, layout=SW128)
static constexpr uint64_t SMEM_DESC_BASE_SW128 =
    (uint64_t(2)  << 61)
    | (uint64_t(1) << 46)
    | (uint64_t(64) << 32)
    | (uint64_t(1) << 16);

#define MAKE_SMEM_DESC(base_addr) \
    (SMEM_DESC_BASE_SW128 | ((uint64_t)((base_addr) >> 4) & 0x3FFF))

#if HAS_TCGEN05
// tcgen05.mma kind::f8f6f4 SS (A smem desc, B smem desc), fp32 accumulate
__device__ __forceinline__ void tcgen05_mma_f8_ss(
    uint32_t d_tmem, uint64_t a_desc, uint64_t b_desc, uint32_t idesc, bool acc)
{
    uint32_t en = acc ? 1u : 0u;
    asm volatile(
        "{\n\t"
        ".reg .pred p;\n\t"
        "setp.ne.u32 p, %5, 0;\n\t"
        "tcgen05.mma.cta_group::1.kind::f8f6f4 [%0], %1, %2, %3, {%4, %4, %4, %4}, p;\n\t"
        "}"
        :: "r"(d_tmem), "l"(a_desc), "l"(b_desc), "r"(idesc), "r"(0u), "r"(en)
        : "memory");
}
#endif

// ============================================================================
// Problem constants
// ============================================================================

static constexpr int M_TOT = 8192;      // B*S
static constexpr int K_TOT = 4096;
static constexpr int N_TOT = 16384;

static constexpr int TM = 128;          // CTA M tile
static constexpr int TN = 256;          // CTA N tile (2 x N=128 MMAs)
static constexpr int KC = 128;          // K chunk (bytes == fp8 elements)
static constexpr int NCHUNK = K_TOT / KC;   // 32
static constexpr int NSTAGES = 4;

static constexpr int A_BYTES = TM * KC;         // 16384
static constexpr int B_BYTES = TN * KC;         // 32768
static constexpr int BH_BYTES = B_BYTES / 2;    // 16384 (per N=128 half)
static constexpr int STAGE_BYTES = A_BYTES + B_BYTES;  // 49152

static constexpr int SMEM_TMEM  = 0;
static constexpr int SMEM_FINAL = 16;
static constexpr int SMEM_FULL0 = 32;   // full[s] = 32 + s*16, empty[s] = 40 + s*16
static constexpr int SMEM_TILE0 = 1024;
static constexpr int SMEM_TOTAL = SMEM_TILE0 + NSTAGES * STAGE_BYTES;  // 197632

static constexpr int TILES_M = M_TOT / TM;   // 64
static constexpr int TILES_N = N_TOT / TN;   // 64
static constexpr int GROUP_M = 8;            // raster grouping for L2 reuse

// idesc for kind::f8f6f4, e4m3 x e4m3 -> f32, M=128, N=128:
// c_format f32 = 1<<4, a_format=b_format=E4M3=0, N>>3 at [17:22], M>>4 at [24:28]
static constexpr uint32_t MMA_IDESC_N128 =
    (1u << 4) | ((uint32_t)(128 / 8) << 17) | ((uint32_t)(TM / 16) << 24);

// Scratch: quantized activations + canonical e4m3 weights
__device__ __align__(256) uint8_t g_Aq[(size_t)M_TOT * K_TOT];
__device__ __align__(256) uint8_t g_Wq[(size_t)N_TOT * K_TOT];
__device__ int g_wmode;   // 0 = raw fp8 bytes, 1 = float32 upcast, 2 = bf16 upcast

// ============================================================================
// Kernel 0: probe weight dtype.
// fp8-exact values upcast to f32 have zero low-20 mantissa bits and |v| < 1.
// fp8-exact values upcast to bf16 have |v| < 1 as bf16.
// Raw e4m3 byte streams fail both tests with overwhelming probability.
// ============================================================================

__global__ void probe_kernel(const uint8_t* __restrict__ w)
{
    if (threadIdx.x != 0 || blockIdx.x != 0) return;
    const uint32_t* wu = reinterpret_cast<const uint32_t*>(w);
    bool is_f32 = true;
    for (int i = 0; i < 64; i++) {
        uint32_t b = wu[i];
        float v = __uint_as_float(b);
        bool ok = (fabsf(v) < 1.0f) && ((b & 0xFFFFFu) == 0u);
        if (!ok) { is_f32 = false; break; }
    }
    if (is_f32) { g_wmode = 1; return; }
    const uint16_t* wh = reinterpret_cast<const uint16_t*>(w);
    bool is_bf16 = true;
    for (int i = 0; i < 128; i++) {
        float v = __uint_as_float(((uint32_t)wh[i]) << 16);
        if (!(fabsf(v) < 1.0f)) { is_bf16 = false; break; }
    }
    g_wmode = is_bf16 ? 2 : 0;
}

// ============================================================================
// Kernel 1: materialize canonical e4m3 weight bytes in g_Wq
// ============================================================================

__global__ void __launch_bounds__(256) wquant_kernel(const uint8_t* __restrict__ w)
{
    int mode = g_wmode;
    const unsigned n16 = (unsigned)(((size_t)N_TOT * K_TOT) / 16u);  // 16 fp8 out / iter
    uint4* __restrict__ ov = reinterpret_cast<uint4*>(g_Wq);
    unsigned stride = blockDim.x * gridDim.x;

    if (mode == 1) {
        const float4* __restrict__ wf = reinterpret_cast<const float4*>(w);
        for (unsigned i = blockIdx.x * blockDim.x + threadIdx.x; i < n16; i += stride) {
            unsigned r[4];
            #pragma unroll
            for (int j = 0; j < 4; j++) {
                float4 v = wf[(size_t)i * 4 + j];
                unsigned p0 = (unsigned)__nv_cvt_float2_to_fp8x2(
                    make_float2(v.x, v.y), __NV_SATFINITE, __NV_E4M3);
                unsigned p1 = (unsigned)__nv_cvt_float2_to_fp8x2(
                    make_float2(v.z, v.w), __NV_SATFINITE, __NV_E4M3);
                r[j] = p0 | (p1 << 16);
            }
            ov[i] = make_uint4(r[0], r[1], r[2], r[3]);
        }
    } else if (mode == 2) {
        const uint4* __restrict__ wb = reinterpret_cast<const uint4*>(w);  // 8 bf16 / uint4
        for (unsigned i = blockIdx.x * blockDim.x + threadIdx.x; i < n16; i += stride) {
            unsigned r[4];
            #pragma unroll
            for (int half = 0; half < 2; half++) {
                uint4 v = wb[(size_t)i * 2 + half];
                unsigned u[4] = {v.x, v.y, v.z, v.w};
                #pragma unroll
                for (int j = 0; j < 2; j++) {
                    float2 f0, f1;
                    f0.x = __uint_as_float((u[j*2+0] & 0xFFFFu) << 16);
                    f0.y = __uint_as_float((u[j*2+0] >> 16) << 16);
                    f1.x = __uint_as_float((u[j*2+1] & 0xFFFFu) << 16);
                    f1.y = __uint_as_float((u[j*2+1] >> 16) << 16);
                    unsigned p0 = (unsigned)__nv_cvt_float2_to_fp8x2(f0, __NV_SATFINITE, __NV_E4M3);
                    unsigned p1 = (unsigned)__nv_cvt_float2_to_fp8x2(f1, __NV_SATFINITE, __NV_E4M3);
                    r[half*2 + j] = p0 | (p1 << 16);
                }
            }
            ov[i] = make_uint4(r[0], r[1], r[2], r[3]);
        }
    } else {
        const uint4* __restrict__ wb = reinterpret_cast<const uint4*>(w);
        for (unsigned i = blockIdx.x * blockDim.x + threadIdx.x; i < n16; i += stride) {
            ov[i] = wb[i];
        }
    }
}

// ============================================================================
// Kernel 2: quantize x (f32) -> e4m3 at x/input_scale
// ============================================================================

__global__ void __launch_bounds__(256) quant_kernel(
    const float* __restrict__ x, const float* __restrict__ s_in)
{
    float inv = 1.0f / __ldg(s_in);
    const unsigned n16 = (unsigned)(((size_t)M_TOT * K_TOT) / 16u);
    const float4* __restrict__ xv = reinterpret_cast<const float4*>(x);
    uint4* __restrict__ ov = reinterpret_cast<uint4*>(g_Aq);
    unsigned stride = blockDim.x * gridDim.x;
    for (unsigned i = blockIdx.x * blockDim.x + threadIdx.x; i < n16; i += stride) {
        unsigned r[4];
        #pragma unroll
        for (int j = 0; j < 4; j++) {
            float4 v = xv[(size_t)i * 4 + j];
            float2 lo = make_float2(v.x * inv, v.y * inv);
            float2 hi = make_float2(v.z * inv, v.w * inv);
            unsigned p0 = (unsigned)__nv_cvt_float2_to_fp8x2(lo, __NV_SATFINITE, __NV_E4M3);
            unsigned p1 = (unsigned)__nv_cvt_float2_to_fp8x2(hi, __NV_SATFINITE, __NV_E4M3);
            r[j] = p0 | (p1 << 16);
        }
        ov[i] = make_uint4(r[0], r[1], r[2], r[3]);
    }
}

// ============================================================================
// Kernel 3: FP8 GEMM, tcgen05 SS, TMA pipelined, D in TMEM
//   out[m, n] = (sum_k Aq[m,k] * Wq[n,k]) * (s_in*s_w) + bias[n]
// ============================================================================

__global__ void __launch_bounds__(128, 1)
#if HAS_TCGEN05
__cluster_dims__(1, 1, 1)
#endif
fp8gemm_kernel(const __grid_constant__ CUtensorMap tma_a,
               const __grid_constant__ CUtensorMap tma_b,
               const float* __restrict__ bias,
               const float* __restrict__ s_in,
               const float* __restrict__ s_w,
               float* __restrict__ out)
{
    extern __shared__ char smem[];
    int tid = threadIdx.x;

    // Grouped tile raster for L2 reuse
    int bid   = blockIdx.x;
    int group = bid / (GROUP_M * TILES_N);
    int inner = bid % (GROUP_M * TILES_N);
    int mt = group * GROUP_M + (inner % GROUP_M);
    int nt = inner / GROUP_M;
    int m0 = mt * TM;
    int n0 = nt * TN;

#if HAS_TCGEN05
    uint32_t sb = smem_to_u32(smem);
    int wid = tid >> 5;
    int lid = tid & 31;

    if (wid == 0) TCGEN05_ALLOC(sb + SMEM_TMEM, 256);
    if (tid == 0) {
        MBARRIER_INIT(sb + SMEM_FINAL, 1);
        #pragma unroll
        for (int s = 0; s < NSTAGES; s++) {
            MBARRIER_INIT(sb + SMEM_FULL0 + s * 16, 1);      // full[s]
            MBARRIER_INIT(sb + SMEM_FULL0 + s * 16 + 8, 1);  // empty[s]
        }
        asm volatile("fence.mbarrier_init.release.cluster;" ::: "memory");
    }
    __syncthreads();

    uint32_t tmem;
    asm volatile("ld.shared.b32 %0, [%1];" : "=r"(tmem) : "r"(sb + SMEM_TMEM));

    if (wid == 0) {
        // ---- TMA producer ----
        if (elect_one_pred()) {
            int stage = 0, phase = 1;   // flipped phase: first empty-wait passes
            for (int c = 0; c < NCHUNK; c++) {
                MBARRIER_WAIT_PARITY_RELAXED(sb + SMEM_FULL0 + stage * 16 + 8, phase);
                MBARRIER_EXPECT_TX(sb + SMEM_FULL0 + stage * 16, STAGE_BYTES);
                uint32_t dstA = sb + SMEM_TILE0 + stage * STAGE_BYTES;
                TMA_LOAD_3D(dstA,           &tma_a, c * KC, m0, 0, sb + SMEM_FULL0 + stage * 16);
                TMA_LOAD_3D(dstA + A_BYTES, &tma_b, c * KC, n0, 0, sb + SMEM_FULL0 + stage * 16);
                if (++stage == NSTAGES) { stage = 0; phase ^= 1; }
            }
        }
    } else if (wid == 1) {
        // ---- MMA issuer: two N=128 MMAs per K-step ----
        if (elect_one_pred()) {
            int stage = 0, phase = 0;
            for (int c = 0; c < NCHUNK; c++) {
                MBARRIER_WAIT_PARITY_RELAXED(sb + SMEM_FULL0 + stage * 16, phase);
                uint32_t base = sb + SMEM_TILE0 + stage * STAGE_BYTES;
                uint64_t ad  = MAKE_SMEM_DESC(base);
                uint64_t bd0 = MAKE_SMEM_DESC(base + A_BYTES);
                uint64_t bd1 = MAKE_SMEM_DESC(base + A_BYTES + BH_BYTES);
                #pragma unroll
                for (int k = 0; k < KC / 32; k++) {
                    bool acc = !(c == 0 && k == 0);
                    tcgen05_mma_f8_ss(tmem,       ad + k * 2, bd0 + k * 2, MMA_IDESC_N128, acc);
                    tcgen05_mma_f8_ss(tmem + 128, ad + k * 2, bd1 + k * 2, MMA_IDESC_N128, acc);
                }
                TCGEN05_COMMIT(sb + SMEM_FULL0 + stage * 16 + 8);
                if (++stage == NSTAGES) { stage = 0; phase ^= 1; }
            }
            TCGEN05_COMMIT(sb + SMEM_FINAL);
        }
    }

    // ---- wait for all MMAs, then epilogue ----
    MBARRIER_WAIT_PARITY(sb + SMEM_FINAL, 0);
    TCGEN05_FENCE_AFTER();

    float scale = __ldg(s_in) * __ldg(s_w);
    int row = wid * 32 + lid;                       // 0..127 (M within tile)
    float* orow = out + (size_t)(m0 + row) * N_TOT + n0;

    #pragma unroll 1
    for (int nb = 0; nb < TN; nb += 32) {
        uint32_t r[32];
        TCGEN05_LD_32X32B_X32(r, tmem + nb);
        TCGEN05_WAIT_LD();
        #pragma unroll
        for (int j = 0; j < 32; j += 4) {
            float4 bv = *reinterpret_cast<const float4*>(bias + n0 + nb + j);
            float4 o;
            o.x = __uint_as_float(r[j + 0]) * scale + bv.x;
            o.y = __uint_as_float(r[j + 1]) * scale + bv.y;
            o.z = __uint_as_float(r[j + 2]) * scale + bv.z;
            o.w = __uint_as_float(r[j + 3]) * scale + bv.w;
            *reinterpret_cast<float4*>(orow + nb + j) = o;
        }
    }

    __syncthreads();
    if (wid == 0) {
        TCGEN05_RELINQUISH_ALLOC_PERMIT();
        TCGEN05_DEALLOC(tmem, 256);
    }
#else
    // ------------------------------------------------------------------
    // Fallback for PTX passes without tcgen05 (plain compute_103).
    // ------------------------------------------------------------------
    (void)tma_a; (void)tma_b;
    float*   lut   = reinterpret_cast<float*>(smem);                    // e4m3 LUT
    uint8_t* wtile = reinterpret_cast<uint8_t*>(smem + 1024);           // 64 x 128 B
    uint8_t* atile = reinterpret_cast<uint8_t*>(smem + 1024 + 64 * KC); // 128 x 128 B

    for (int i = tid; i < 256; i += 128) {
        __half_raw hr = __nv_cvt_fp8_to_halfraw((__nv_fp8_storage_t)i, __NV_E4M3);
        lut[i] = __half2float(*reinterpret_cast<__half*>(&hr));
    }
    __syncthreads();

    float scale = __ldg(s_in) * __ldg(s_w);
    int row = m0 + tid;

    for (int cb = 0; cb < TN / 64; cb++) {
        int nb = n0 + cb * 64;
        float acc[64];
        #pragma unroll
        for (int j = 0; j < 64; j++) acc[j] = 0.0f;

        for (int c = 0; c < NCHUNK; c++) {
            __syncthreads();
            for (int idx = tid; idx < 64 * (KC / 4); idx += 128) {
                int r = idx / (KC / 4), j = idx % (KC / 4);
                reinterpret_cast<uint32_t*>(wtile)[idx] =
                    reinterpret_cast<const uint32_t*>(g_Wq + (size_t)(nb + r) * K_TOT + c * KC)[j];
            }
            for (int j = 0; j < KC / 4; j++) {
                reinterpret_cast<uint32_t*>(atile)[tid * (KC / 4) + j] =
                    reinterpret_cast<const uint32_t*>(g_Aq + (size_t)row * K_TOT + c * KC)[j];
            }
            __syncthreads();

            for (int n = 0; n < 64; n++) {
                float s = 0.0f;
                const uint32_t* wr = reinterpret_cast<const uint32_t*>(wtile + n * KC);
                const uint32_t* ar = reinterpret_cast<const uint32_t*>(atile + tid * KC);
                for (int k4 = 0; k4 < KC / 4; k4++) {
                    uint32_t av = ar[k4], wv = wr[k4];
                    s += lut[av & 0xFF]         * lut[wv & 0xFF];
                    s += lut[(av >> 8) & 0xFF]  * lut[(wv >> 8) & 0xFF];
                    s += lut[(av >> 16) & 0xFF] * lut[(wv >> 16) & 0xFF];
                    s += lut[(av >> 24) & 0xFF] * lut[(wv >> 24) & 0xFF];
                }
                acc[n] += s;
            }
        }

        float* orow = out + (size_t)row * N_TOT + nb;
        for (int n = 0; n < 64; n++)
            orow[n] = acc[n] * scale + __ldg(bias + nb + n);
        __syncthreads();
    }
#endif
}

// ============================================================================
// Host launch
// ============================================================================

typedef CUresult (*cuTensorMapEncodeTiled_t)(
    CUtensorMap*, CUtensorMapDataType, cuuint32_t, void*,
    const cuuint64_t*, const cuuint64_t*, const cuuint32_t*, const cuuint32_t*,
    CUtensorMapInterleave, CUtensorMapSwizzle, CUtensorMapL2promotion,
    CUtensorMapFloatOOBfill);

static cuTensorMapEncodeTiled_t get_encode_fn() {
    void* fn = nullptr;
    cudaDriverEntryPointQueryResult st;
#if CUDART_VERSION >= 12050
    cudaGetDriverEntryPointByVersion("cuTensorMapEncodeTiled", &fn, 12000,
                                     cudaEnableDefault, &st);
#else
    cudaGetDriverEntryPoint("cuTensorMapEncodeTiled", &fn, cudaEnableDefault, &st);
#endif
    return (cuTensorMapEncodeTiled_t)fn;
}

static void encode_fp8_map(cuTensorMapEncodeTiled_t enc, CUtensorMap* out_map,
                           void* base, uint64_t rows, uint32_t box_rows) {
    uint64_t dims[3]    = {(uint64_t)K_TOT, rows, 1};
    uint64_t strides[2] = {(uint64_t)K_TOT, (uint64_t)K_TOT * rows};
    uint32_t box[3]     = {(uint32_t)KC, box_rows, 1};
    uint32_t estr[3]    = {1, 1, 1};
    enc(out_map, CU_TENSOR_MAP_DATA_TYPE_UINT8, 3, base,
        dims, strides, box, estr,
        CU_TENSOR_MAP_INTERLEAVE_NONE, CU_TENSOR_MAP_SWIZZLE_128B,
        CU_TENSOR_MAP_L2_PROMOTION_L2_128B, CU_TENSOR_MAP_FLOAT_OOB_FILL_NONE);
}

extern "C" void kernel_launch(void* const* d_in, const int* in_sizes, int n_in,
                              void* d_out, int out_size) {
    const float* x    = (const float*)d_in[0];
    const uint8_t* w  = (const uint8_t*)d_in[1];  // fp8 weights (raw / f32 / bf16)
    const float* bias = (const float*)d_in[2];
    const float* s_in = (const float*)d_in[3];
    const float* s_w  = (const float*)d_in[4];
    float* out        = (float*)d_out;

    // 0) probe weight encoding, 1) canonicalize weights, 2) quantize x
    probe_kernel<<<1, 32>>>(w);
    wquant_kernel<<<4096, 256>>>(w);
    quant_kernel<<<2048, 256>>>(x, s_in);

    // TMA descriptors over canonical fp8 scratch
    void* aq_ptr = nullptr;
    void* wq_ptr = nullptr;
    cudaGetSymbolAddress(&aq_ptr, g_Aq);
    cudaGetSymbolAddress(&wq_ptr, g_Wq);
    cuTensorMapEncodeTiled_t enc = get_encode_fn();
    CUtensorMap tma_a, tma_b;
    encode_fp8_map(enc, &tma_a, aq_ptr, (uint64_t)M_TOT, (uint32_t)TM);
    encode_fp8_map(enc, &tma_b, wq_ptr, (uint64_t)N_TOT, (uint32_t)TN);

    // 3) GEMM
    cudaFuncSetAttribute(fp8gemm_kernel,
                         cudaFuncAttributeMaxDynamicSharedMemorySize, SMEM_TOTAL);
    fp8gemm_kernel<<<TILES_M * TILES_N, 128, SMEM_TOTAL>>>(
        tma_a, tma_b, bias, s_in, s_w, out);
}

// round 4
// speedup vs baseline: 1.1511x; 1.1511x over previous
#include <cuda_runtime.h>
#include <cuda.h>
#include <cuda_fp8.h>
#include <cuda_fp16.h>
#include <cuda_bf16.h>
#include <cstdint>
#include <cstdio>

// ============================================================================
// Arch-feature gate: tcgen05 / .cta_group are only legal in PTX modules whose
// virtual arch is arch-specific (compute_103a) or family-specific (compute_103f).
// ============================================================================
#if defined(__CUDA_ARCH__) && \
    (defined(__CUDA_ARCH_FEAT_SM103_ALL) || defined(__CUDA_ARCH_FEAT_SM100_ALL) || \
     defined(__CUDA_ARCH_SPECIFIC__) || defined(__CUDA_ARCH_FAMILY_SPECIFIC__))
#define HAS_TCGEN05 1
#else
#define HAS_TCGEN05 0
#endif

// ============================================================================
// Helpers
// ============================================================================

__device__ __forceinline__ uint32_t elect_one_pred() {
    uint32_t pred;
    asm volatile(
        "{\n\t"
        ".reg .pred p;\n\t"
        "elect.sync _|p, 0xFFFFFFFF;\n\t"
        "selp.b32 %0, 1, 0, p;\n\t"
        "}"
        : "=r"(pred));
    return pred;
}

__device__ __forceinline__ uint32_t smem_to_u32(const void* smem_ptr) {
    uint32_t addr;
    asm("{ .reg .u64 tmp; cvta.to.shared.u64 tmp, %1; cvt.u32.u64 %0, tmp; }"
        : "=r"(addr) : "l"(smem_ptr));
    return addr;
}

__device__ __forceinline__ uint32_t cluster_ctarank_u32() {
    uint32_t r;
    asm("mov.u32 %0, %%cluster_ctarank;" : "=r"(r));
    return r;
}

#define MBARRIER_INIT(mbar, count) \
    asm volatile("mbarrier.init.shared.b64 [%0], %1;" \
                 :: "r"((uint32_t)(mbar)), "r"((uint32_t)(count)) : "memory")

#define MBARRIER_EXPECT_TX(mbar, tx_bytes) \
    asm volatile("mbarrier.arrive.expect_tx.shared.b64 _, [%0], %1;" \
                 :: "r"((uint32_t)(mbar)), "r"((uint32_t)(tx_bytes)) : "memory")

#define MBARRIER_WAIT_PARITY(mbar, parity) do {                                  \
    uint32_t _mbar = (uint32_t)(mbar);                                           \
    uint32_t _par  = (uint32_t)(parity);                                         \
    asm volatile(                                                                \
        "{\n\t"                                                                  \
        ".reg .pred P1;\n\t"                                                     \
        "WAIT_LOOP_%=:\n\t"                                                      \
        "mbarrier.try_wait.parity.acquire.cta.shared::cta.b64 P1, [%0], %1, 0x989680;\n\t" \
        "@P1 bra.uni WAIT_DONE_%=;\n\t"                                          \
        "bra.uni WAIT_LOOP_%=;\n\t"                                              \
        "WAIT_DONE_%=:\n\t"                                                      \
        "}"                                                                      \
        :: "r"(_mbar), "r"(_par) : "memory");                                    \
} while (0)

#define MBARRIER_WAIT_PARITY_RELAXED(mbar, parity) do {                          \
    uint32_t _mbar = (uint32_t)(mbar);                                           \
    uint32_t _par  = (uint32_t)(parity);                                         \
    asm volatile(                                                                \
        "{\n\t"                                                                  \
        ".reg .pred P1;\n\t"                                                     \
        "WAIT_LOOP_%=:\n\t"                                                      \
        "mbarrier.try_wait.parity.relaxed.cta.shared::cta.b64 P1, [%0], %1, 0x989680;\n\t" \
        "@P1 bra.uni WAIT_DONE_%=;\n\t"                                          \
        "bra.uni WAIT_LOOP_%=;\n\t"                                              \
        "WAIT_DONE_%=:\n\t"                                                      \
        "}"                                                                      \
        :: "r"(_mbar), "r"(_par) : "memory");                                    \
} while (0)

// cg2 TMA load: both CTAs execute; complete_tx targets the LEADER CTA's
// barrier (bit 24 of the barrier address cleared).
#define TMA_LOAD_3D_CG2(smem_addr, tensor_map, cx, cy, cz, mbar) \
    asm volatile( \
        "{\n\t" \
        ".reg .b32 leaderBar;\n\t" \
        "and.b32 leaderBar, %5, 0xFEFFFFFF;\n\t" \
        "cp.async.bulk.tensor.3d.cta_group::2.shared::cluster.global" \
        ".tile.mbarrier::complete_tx::bytes " \
        "[%0], [%1, {%2, %3, %4}], [leaderBar];\n\t" \
        "}" \
        :: "r"((uint32_t)(smem_addr)), "l"(tensor_map), \
           "r"((int32_t)(cx)), "r"((int32_t)(cy)), "r"((int32_t)(cz)), \
           "r"((uint32_t)(mbar)) \
        : "memory")

#define TCGEN05_ALLOC_CG2(smem_result_addr, nCols) \
    asm volatile("tcgen05.alloc.cta_group::2.sync.aligned.shared::cta.b32 [%0], %1;" \
                 :: "r"((uint32_t)(smem_result_addr)), "r"((uint32_t)(nCols)) : "memory")

#define TCGEN05_DEALLOC_CG2(tmem_addr, nCols) \
    asm volatile("tcgen05.dealloc.cta_group::2.sync.aligned.b32 %0, %1;" \
                 :: "r"(tmem_addr), "r"((uint32_t)(nCols)))

#define TCGEN05_RELINQUISH_ALLOC_PERMIT_CG2() \
    asm volatile("tcgen05.relinquish_alloc_permit.cta_group::2.sync.aligned;")

#define TCGEN05_COMMIT_MULTICAST_CG2(mbar, cta_mask) \
    asm volatile( \
        "tcgen05.commit.cta_group::2.mbarrier::arrive::one.shared::cluster.multicast::cluster.b64 [%0], %1;" \
        :: "r"((uint32_t)(mbar)), "h"((uint16_t)(cta_mask)) : "memory")

#define TCGEN05_FENCE_AFTER() \
    asm volatile("tcgen05.fence::after_thread_sync;" ::: "memory")

#define TCGEN05_WAIT_LD() \
    asm volatile("tcgen05.wait::ld.sync.aligned;" ::: "memory")

#define CLUSTER_SYNC() do { \
    asm volatile("barrier.cluster.arrive.aligned;" ::: "memory"); \
    asm volatile("barrier.cluster.wait.aligned;" ::: "memory"); \
} while (0)

#define TCGEN05_LD_32X32B_X32(r, tmem_addr) \
    asm volatile( \
        "tcgen05.ld.sync.aligned.32x32b.x32.b32 " \
        "{%0, %1, %2, %3, %4, %5, %6, %7, " \
        " %8, %9, %10, %11, %12, %13, %14, %15, " \
        " %16, %17, %18, %19, %20, %21, %22, %23, " \
        " %24, %25, %26, %27, %28, %29, %30, %31}, [%32];" \
        : "=r"((r)[0]),  "=r"((r)[1]),  "=r"((r)[2]),  "=r"((r)[3]), \
          "=r"((r)[4]),  "=r"((r)[5]),  "=r"((r)[6]),  "=r"((r)[7]), \
          "=r"((r)[8]),  "=r"((r)[9]),  "=r"((r)[10]), "=r"((r)[11]), \
          "=r"((r)[12]), "=r"((r)[13]), "=r"((r)[14]), "=r"((r)[15]), \
          "=r"((r)[16]), "=r"((r)[17]), "=r"((r)[18]), "=r"((r)[19]), \
          "=r"((r)[20]), "=r"((r)[21]), "=r"((r)[22]), "=r"((r)[23]), \
          "=r"((r)[24]), "=r"((r)[25]), "=r"((r)[26]), "=r"((r)[27]), \
          "=r"((r)[28]), "=r"((r)[29]), "=r"((r)[30]), "=r"((r)[31]) \
        : "r"(tmem_addr))

// SW128 K-major SMEM descriptor (LBO=1, SBO=64, version=1, layout=SW128)
static constexpr uint64_t SMEM_DESC_BASE_SW128 =
    (uint64_t(2)  << 61)
    | (uint64_t(1) << 46)
    | (uint64_t(64) << 32)
    | (uint64_t(1) << 16);

#define MAKE_SMEM_DESC(base_addr) \
    (SMEM_DESC_BASE_SW128 | ((uint64_t)((base_addr) >> 4) & 0x3FFF))

#if HAS_TCGEN05
// tcgen05.mma cta_group::2 kind::f8f6f4 SS, fp32 accumulate.
// cg2 requires the 8-register disable-output-lane list.
__device__ __forceinline__ void tcgen05_mma_f8_ss_cg2(
    uint32_t d_tmem, uint64_t a_desc, uint64_t b_desc, uint32_t idesc, bool acc)
{
    uint32_t en = acc ? 1u : 0u;
    asm volatile(
        "{\n\t"
        ".reg .pred p;\n\t"
        "setp.ne.u32 p, %5, 0;\n\t"
        "tcgen05.mma.cta_group::2.kind::f8f6f4 [%0], %1, %2, %3, "
        "{%4, %4, %4, %4, %4, %4, %4, %4}, p;\n\t"
        "}"
        :: "r"(d_tmem), "l"(a_desc), "l"(b_desc), "r"(idesc), "r"(0u), "r"(en)
        : "memory");
}
#endif

// ============================================================================
// Problem constants
// ============================================================================

static constexpr int M_TOT = 8192;      // B*S
static constexpr int K_TOT = 4096;
static constexpr int N_TOT = 16384;

static constexpr int TMP   = 256;       // M tile per CTA pair (128 per CTA)
static constexpr int TN    = 512;       // N tile per pair (2 x N=256 cg2 MMAs)
static constexpr int MMA_N = 256;
static constexpr int KC    = 128;       // K chunk (bytes == fp8 elements)
static constexpr int NCHUNK = K_TOT / KC;   // 32
static constexpr int NSTAGES = 4;

static constexpr int A_BYTES = 128 * KC;        // 16384 (per-CTA A half)
static constexpr int BSEG    = 128 * KC;        // 16384 (per-CTA half of one N=256 atom)
static constexpr int STAGE_BYTES = A_BYTES + 2 * BSEG;   // 49152 per CTA
static constexpr int PAIR_STAGE_TX = 2 * STAGE_BYTES;    // 98304 (leader barrier tx)

static constexpr int SMEM_TMEM  = 0;
static constexpr int SMEM_FINAL = 16;
static constexpr int SMEM_FULL0 = 32;   // full[s] = 32 + s*16, empty[s] = 40 + s*16
static constexpr int SMEM_TILE0 = 1024;
static constexpr int SMEM_TOTAL = SMEM_TILE0 + NSTAGES * STAGE_BYTES;  // 197632

static constexpr int TILES_MP = M_TOT / TMP;   // 32 m-pairs
static constexpr int TILES_NT = N_TOT / TN;    // 32 n-tiles
static constexpr int GROUP_MP = 8;             // raster grouping for L2 reuse

// idesc for cg2 kind::f8f6f4, e4m3 x e4m3 -> f32, M=256, N=256:
// c_format f32 = 1<<4, a/b_format E4M3 = 0, N>>3 at [17:22], M>>4 at [24:28]
static constexpr uint32_t MMA_IDESC_CG2 =
    (1u << 4) | ((uint32_t)(MMA_N / 8) << 17) | ((uint32_t)(TMP / 16) << 24);

// Scratch: quantized activations + canonical e4m3 weights
__device__ __align__(256) uint8_t g_Aq[(size_t)M_TOT * K_TOT];
__device__ __align__(256) uint8_t g_Wq[(size_t)N_TOT * K_TOT];
__device__ int g_wmode;   // 0 = raw fp8 bytes, 1 = float32 upcast, 2 = bf16 upcast

// ============================================================================
// Kernel 0: probe weight dtype (see R2 post-mortem).
// ============================================================================

__global__ void probe_kernel(const uint8_t* __restrict__ w)
{
    if (threadIdx.x != 0 || blockIdx.x != 0) return;
    const uint32_t* wu = reinterpret_cast<const uint32_t*>(w);
    bool is_f32 = true;
    for (int i = 0; i < 64; i++) {
        uint32_t b = wu[i];
        float v = __uint_as_float(b);
        bool ok = (fabsf(v) < 1.0f) && ((b & 0xFFFFFu) == 0u);
        if (!ok) { is_f32 = false; break; }
    }
    if (is_f32) { g_wmode = 1; return; }
    const uint16_t* wh = reinterpret_cast<const uint16_t*>(w);
    bool is_bf16 = true;
    for (int i = 0; i < 128; i++) {
        float v = __uint_as_float(((uint32_t)wh[i]) << 16);
        if (!(fabsf(v) < 1.0f)) { is_bf16 = false; break; }
    }
    g_wmode = is_bf16 ? 2 : 0;
}

// ============================================================================
// Kernel 1: materialize canonical e4m3 weight bytes in g_Wq
// ============================================================================

__global__ void __launch_bounds__(256) wquant_kernel(const uint8_t* __restrict__ w)
{
    int mode = g_wmode;
    const unsigned n16 = (unsigned)(((size_t)N_TOT * K_TOT) / 16u);  // 16 fp8 out / iter
    uint4* __restrict__ ov = reinterpret_cast<uint4*>(g_Wq);
    unsigned stride = blockDim.x * gridDim.x;

    if (mode == 1) {
        const float4* __restrict__ wf = reinterpret_cast<const float4*>(w);
        for (unsigned i = blockIdx.x * blockDim.x + threadIdx.x; i < n16; i += stride) {
            unsigned r[4];
            #pragma unroll
            for (int j = 0; j < 4; j++) {
                float4 v = wf[(size_t)i * 4 + j];
                unsigned p0 = (unsigned)__nv_cvt_float2_to_fp8x2(
                    make_float2(v.x, v.y), __NV_SATFINITE, __NV_E4M3);
                unsigned p1 = (unsigned)__nv_cvt_float2_to_fp8x2(
                    make_float2(v.z, v.w), __NV_SATFINITE, __NV_E4M3);
                r[j] = p0 | (p1 << 16);
            }
            ov[i] = make_uint4(r[0], r[1], r[2], r[3]);
        }
    } else if (mode == 2) {
        const uint4* __restrict__ wb = reinterpret_cast<const uint4*>(w);  // 8 bf16 / uint4
        for (unsigned i = blockIdx.x * blockDim.x + threadIdx.x; i < n16; i += stride) {
            unsigned r[4];
            #pragma unroll
            for (int half = 0; half < 2; half++) {
                uint4 v = wb[(size_t)i * 2 + half];
                unsigned u[4] = {v.x, v.y, v.z, v.w};
                #pragma unroll
                for (int j = 0; j < 2; j++) {
                    float2 f0, f1;
                    f0.x = __uint_as_float((u[j*2+0] & 0xFFFFu) << 16);
                    f0.y = __uint_as_float((u[j*2+0] >> 16) << 16);
                    f1.x = __uint_as_float((u[j*2+1] & 0xFFFFu) << 16);
                    f1.y = __uint_as_float((u[j*2+1] >> 16) << 16);
                    unsigned p0 = (unsigned)__nv_cvt_float2_to_fp8x2(f0, __NV_SATFINITE, __NV_E4M3);
                    unsigned p1 = (unsigned)__nv_cvt_float2_to_fp8x2(f1, __NV_SATFINITE, __NV_E4M3);
                    r[half*2 + j] = p0 | (p1 << 16);
                }
            }
            ov[i] = make_uint4(r[0], r[1], r[2], r[3]);
        }
    } else {
        const uint4* __restrict__ wb = reinterpret_cast<const uint4*>(w);
        for (unsigned i = blockIdx.x * blockDim.x + threadIdx.x; i < n16; i += stride) {
            ov[i] = wb[i];
        }
    }
}

// ============================================================================
// Kernel 2: quantize x (f32) -> e4m3 at x/input_scale
// ============================================================================

__global__ void __launch_bounds__(256) quant_kernel(
    const float* __restrict__ x, const float* __restrict__ s_in)
{
    float inv = 1.0f / __ldg(s_in);
    const unsigned n16 = (unsigned)(((size_t)M_TOT * K_TOT) / 16u);
    const float4* __restrict__ xv = reinterpret_cast<const float4*>(x);
    uint4* __restrict__ ov = reinterpret_cast<uint4*>(g_Aq);
    unsigned stride = blockDim.x * gridDim.x;
    for (unsigned i = blockIdx.x * blockDim.x + threadIdx.x; i < n16; i += stride) {
        unsigned r[4];
        #pragma unroll
        for (int j = 0; j < 4; j++) {
            float4 v = xv[(size_t)i * 4 + j];
            float2 lo = make_float2(v.x * inv, v.y * inv);
            float2 hi = make_float2(v.z * inv, v.w * inv);
            unsigned p0 = (unsigned)__nv_cvt_float2_to_fp8x2(lo, __NV_SATFINITE, __NV_E4M3);
            unsigned p1 = (unsigned)__nv_cvt_float2_to_fp8x2(hi, __NV_SATFINITE, __NV_E4M3);
            r[j] = p0 | (p1 << 16);
        }
        ov[i] = make_uint4(r[0], r[1], r[2], r[3]);
    }
}

// ============================================================================
// Kernel 3: FP8 GEMM, 2-CTA tcgen05 MMA (M=256 per pair, N=512 per tile).
//   B-split: each N=256 atom reads N/2=128 rows from each CTA at the same
//   SMEM offset (hence per-CTA B segments hold rows [j*256 + rank*128, +128)).
// ============================================================================

__global__ void __launch_bounds__(128, 1) __cluster_dims__(2, 1, 1)
fp8gemm_kernel(const __grid_constant__ CUtensorMap tma_a,
               const __grid_constant__ CUtensorMap tma_b,
               const float* __restrict__ bias,
               const float* __restrict__ s_in,
               const float* __restrict__ s_w,
               float* __restrict__ out)
{
    extern __shared__ char smem[];
    int tid = threadIdx.x;

    // Pair raster: GROUP_MP m-pairs per group, sweep n within a group.
    int pair  = blockIdx.x >> 1;
    int group = pair / (GROUP_MP * TILES_NT);
    int inner = pair % (GROUP_MP * TILES_NT);
    int mp = group * GROUP_MP + (inner % GROUP_MP);
    int nt = inner / GROUP_MP;
    int m0 = mp * TMP;
    int n0 = nt * TN;

#if HAS_TCGEN05
    uint32_t sb = smem_to_u32(smem);
    int wid = tid >> 5;
    int lid = tid & 31;
    uint32_t rank = cluster_ctarank_u32();

    if (wid == 0) TCGEN05_ALLOC_CG2(sb + SMEM_TMEM, 512);
    if (tid == 0) {
        MBARRIER_INIT(sb + SMEM_FINAL, 1);
        #pragma unroll
        for (int s = 0; s < NSTAGES; s++) {
            MBARRIER_INIT(sb + SMEM_FULL0 + s * 16, 1);      // full[s] (leader-resident)
            MBARRIER_INIT(sb + SMEM_FULL0 + s * 16 + 8, 1);  // empty[s] (per-CTA)
        }
        asm volatile("fence.mbarrier_init.release.cluster;" ::: "memory");
    }
    __syncthreads();
    // All barriers in both CTAs must be live before any cross-CTA TMA/commit.
    CLUSTER_SYNC();

    uint32_t tmem;
    asm volatile("ld.shared.b32 %0, [%1];" : "=r"(tmem) : "r"(sb + SMEM_TMEM));

    if (wid == 0) {
        // ---- TMA producer (both CTAs; completes target leader full[s]) ----
        if (elect_one_pred()) {
            int stage = 0, phase = 1;   // flipped phase: first empty-wait passes
            for (int c = 0; c < NCHUNK; c++) {
                MBARRIER_WAIT_PARITY_RELAXED(sb + SMEM_FULL0 + stage * 16 + 8, phase);
                if (rank == 0)
                    MBARRIER_EXPECT_TX(sb + SMEM_FULL0 + stage * 16, PAIR_STAGE_TX);
                uint32_t dst = sb + SMEM_TILE0 + stage * STAGE_BYTES;
                uint32_t fullbar = sb + SMEM_FULL0 + stage * 16;
                // A half: this CTA's 128 M-rows
                TMA_LOAD_3D_CG2(dst, &tma_a, c * KC, m0 + (int)rank * 128, 0, fullbar);
                // B halves: rows [n0 + j*256 + rank*128, +128) for atom j
                TMA_LOAD_3D_CG2(dst + A_BYTES, &tma_b,
                                c * KC, n0 + (int)rank * 128, 0, fullbar);
                TMA_LOAD_3D_CG2(dst + A_BYTES + BSEG, &tma_b,
                                c * KC, n0 + 256 + (int)rank * 128, 0, fullbar);
                if (++stage == NSTAGES) { stage = 0; phase ^= 1; }
            }
        }
    } else if (wid == 1 && rank == 0) {
        // ---- MMA issuer (leader only): two N=256 cg2 MMAs per K-step ----
        if (elect_one_pred()) {
            int stage = 0, phase = 0;
            for (int c = 0; c < NCHUNK; c++) {
                MBARRIER_WAIT_PARITY_RELAXED(sb + SMEM_FULL0 + stage * 16, phase);
                uint32_t base = sb + SMEM_TILE0 + stage * STAGE_BYTES;
                uint64_t ad  = MAKE_SMEM_DESC(base);
                uint64_t bd0 = MAKE_SMEM_DESC(base + A_BYTES);
                uint64_t bd1 = MAKE_SMEM_DESC(base + A_BYTES + BSEG);
                #pragma unroll
                for (int k = 0; k < KC / 32; k++) {
                    bool acc = !(c == 0 && k == 0);
                    tcgen05_mma_f8_ss_cg2(tmem,       ad + k * 2, bd0 + k * 2, MMA_IDESC_CG2, acc);
                    tcgen05_mma_f8_ss_cg2(tmem + 256, ad + k * 2, bd1 + k * 2, MMA_IDESC_CG2, acc);
                }
                // Release stage s in BOTH CTAs once the MMAs have consumed it.
                TCGEN05_COMMIT_MULTICAST_CG2(sb + SMEM_FULL0 + stage * 16 + 8, 0x3);
                if (++stage == NSTAGES) { stage = 0; phase ^= 1; }
            }
            TCGEN05_COMMIT_MULTICAST_CG2(sb + SMEM_FINAL, 0x3);
        }
    }

    // ---- wait for all MMAs, then epilogue (each CTA reads its own TMEM) ----
    MBARRIER_WAIT_PARITY(sb + SMEM_FINAL, 0);
    TCGEN05_FENCE_AFTER();

    float scale = __ldg(s_in) * __ldg(s_w);
    int row = wid * 32 + lid;                          // 0..127 (M within CTA half)
    float* orow = out + (size_t)(m0 + (int)rank * 128 + row) * N_TOT + n0;

    #pragma unroll 1
    for (int nb = 0; nb < TN; nb += 32) {
        uint32_t r[32];
        TCGEN05_LD_32X32B_X32(r, tmem + nb);
        TCGEN05_WAIT_LD();
        #pragma unroll
        for (int j = 0; j < 32; j += 4) {
            float4 bv = *reinterpret_cast<const float4*>(bias + n0 + nb + j);
            float4 o;
            o.x = __uint_as_float(r[j + 0]) * scale + bv.x;
            o.y = __uint_as_float(r[j + 1]) * scale + bv.y;
            o.z = __uint_as_float(r[j + 2]) * scale + bv.z;
            o.w = __uint_as_float(r[j + 3]) * scale + bv.w;
            *reinterpret_cast<float4*>(orow + nb + j) = o;
        }
    }

    __syncthreads();
    if (wid == 0) {
        TCGEN05_RELINQUISH_ALLOC_PERMIT_CG2();
        TCGEN05_DEALLOC_CG2(tmem, 512);
    }
    // No CTA may exit while its peer's TMA/commit could still target it.
    CLUSTER_SYNC();
#else
    // ------------------------------------------------------------------
    // Fallback for PTX passes without tcgen05 (plain compute_103).
    // ------------------------------------------------------------------
    (void)tma_a; (void)tma_b;
    int rank = blockIdx.x & 1;
    float*   lut   = reinterpret_cast<float*>(smem);                    // e4m3 LUT
    uint8_t* wtile = reinterpret_cast<uint8_t*>(smem + 1024);           // 64 x 128 B
    uint8_t* atile = reinterpret_cast<uint8_t*>(smem + 1024 + 64 * KC); // 128 x 128 B

    for (int i = tid; i < 256; i += 128) {
        __half_raw hr = __nv_cvt_fp8_to_halfraw((__nv_fp8_storage_t)i, __NV_E4M3);
        lut[i] = __half2float(*reinterpret_cast<__half*>(&hr));
    }
    __syncthreads();

    float scale = __ldg(s_in) * __ldg(s_w);
    int row = m0 + rank * 128 + tid;

    for (int cb = 0; cb < TN / 64; cb++) {
        int nb = n0 + cb * 64;
        float acc[64];
        #pragma unroll
        for (int j = 0; j < 64; j++) acc[j] = 0.0f;

        for (int c = 0; c < NCHUNK; c++) {
            __syncthreads();
            for (int idx = tid; idx < 64 * (KC / 4); idx += 128) {
                int r = idx / (KC / 4), j = idx % (KC / 4);
                reinterpret_cast<uint32_t*>(wtile)[idx] =
                    reinterpret_cast<const uint32_t*>(g_Wq + (size_t)(nb + r) * K_TOT + c * KC)[j];
            }
            for (int j = 0; j < KC / 4; j++) {
                reinterpret_cast<uint32_t*>(atile)[tid * (KC / 4) + j] =
                    reinterpret_cast<const uint32_t*>(g_Aq + (size_t)row * K_TOT + c * KC)[j];
            }
            __syncthreads();

            for (int n = 0; n < 64; n++) {
                float s = 0.0f;
                const uint32_t* wr = reinterpret_cast<const uint32_t*>(wtile + n * KC);
                const uint32_t* ar = reinterpret_cast<const uint32_t*>(atile + tid * KC);
                for (int k4 = 0; k4 < KC / 4; k4++) {
                    uint32_t av = ar[k4], wv = wr[k4];
                    s += lut[av & 0xFF]         * lut[wv & 0xFF];
                    s += lut[(av >> 8) & 0xFF]  * lut[(wv >> 8) & 0xFF];
                    s += lut[(av >> 16) & 0xFF] * lut[(wv >> 16) & 0xFF];
                    s += lut[(av >> 24) & 0xFF] * lut[(wv >> 24) & 0xFF];
                }
                acc[n] += s;
            }
        }

        float* orow = out + (size_t)row * N_TOT + nb;
        for (int n = 0; n < 64; n++)
            orow[n] = acc[n] * scale + __ldg(bias + nb + n);
        __syncthreads();
    }
#endif
}

// ============================================================================
// Host launch
// ============================================================================

typedef CUresult (*cuTensorMapEncodeTiled_t)(
    CUtensorMap*, CUtensorMapDataType, cuuint32_t, void*,
    const cuuint64_t*, const cuuint64_t*, const cuuint32_t*, const cuuint32_t*,
    CUtensorMapInterleave, CUtensorMapSwizzle, CUtensorMapL2promotion,
    CUtensorMapFloatOOBfill);

static cuTensorMapEncodeTiled_t get_encode_fn() {
    void* fn = nullptr;
    cudaDriverEntryPointQueryResult st;
#if CUDART_VERSION >= 12050
    cudaGetDriverEntryPointByVersion("cuTensorMapEncodeTiled", &fn, 12000,
                                     cudaEnableDefault, &st);
#else
    cudaGetDriverEntryPoint("cuTensorMapEncodeTiled", &fn, cudaEnableDefault, &st);
#endif
    return (cuTensorMapEncodeTiled_t)fn;
}

static void encode_fp8_map(cuTensorMapEncodeTiled_t enc, CUtensorMap* out_map,
                           void* base, uint64_t rows) {
    uint64_t dims[3]    = {(uint64_t)K_TOT, rows, 1};
    uint64_t strides[2] = {(uint64_t)K_TOT, (uint64_t)K_TOT * rows};
    uint32_t box[3]     = {(uint32_t)KC, 128, 1};
    uint32_t estr[3]    = {1, 1, 1};
    enc(out_map, CU_TENSOR_MAP_DATA_TYPE_UINT8, 3, base,
        dims, strides, box, estr,
        CU_TENSOR_MAP_INTERLEAVE_NONE, CU_TENSOR_MAP_SWIZZLE_128B,
        CU_TENSOR_MAP_L2_PROMOTION_L2_128B, CU_TENSOR_MAP_FLOAT_OOB_FILL_NONE);
}

extern "C" void kernel_launch(void* const* d_in, const int* in_sizes, int n_in,
                              void* d_out, int out_size) {
    const float* x    = (const float*)d_in[0];
    const uint8_t* w  = (const uint8_t*)d_in[1];  // fp8 weights (raw / f32 / bf16)
    const float* bias = (const float*)d_in[2];
    const float* s_in = (const float*)d_in[3];
    const float* s_w  = (const float*)d_in[4];
    float* out        = (float*)d_out;

    // 0) probe weight encoding, 1) canonicalize weights, 2) quantize x
    probe_kernel<<<1, 32>>>(w);
    wquant_kernel<<<4096, 256>>>(w);
    quant_kernel<<<2048, 256>>>(x, s_in);

    // TMA descriptors over canonical fp8 scratch
    void* aq_ptr = nullptr;
    void* wq_ptr = nullptr;
    cudaGetSymbolAddress(&aq_ptr, g_Aq);
    cudaGetSymbolAddress(&wq_ptr, g_Wq);
    cuTensorMapEncodeTiled_t enc = get_encode_fn();
    CUtensorMap tma_a, tma_b;
    encode_fp8_map(enc, &tma_a, aq_ptr, (uint64_t)M_TOT);
    encode_fp8_map(enc, &tma_b, wq_ptr, (uint64_t)N_TOT);

    // 3) GEMM: 2048 CTAs = 1024 cluster pairs (cluster dims are static).
    cudaFuncSetAttribute(fp8gemm_kernel,
                         cudaFuncAttributeMaxDynamicSharedMemorySize, SMEM_TOTAL);
    fp8gemm_kernel<<<TILES_MP * TILES_NT * 2, 128, SMEM_TOTAL>>>(
        tma_a, tma_b, bias, s_in, s_w, out);
}

// round 5
// speedup vs baseline: 1.2510x; 1.0867x over previous
#include <cuda_runtime.h>
#include <cuda.h>
#include <cuda_fp8.h>
#include <cuda_fp16.h>
#include <cuda_bf16.h>
#include <cstdint>
#include <cstdio>

// ============================================================================
// Arch-feature gate (see R1 post-mortem).
// ============================================================================
#if defined(__CUDA_ARCH__) && \
    (defined(__CUDA_ARCH_FEAT_SM103_ALL) || defined(__CUDA_ARCH_FEAT_SM100_ALL) || \
     defined(__CUDA_ARCH_SPECIFIC__) || defined(__CUDA_ARCH_FAMILY_SPECIFIC__))
#define HAS_TCGEN05 1
#else
#define HAS_TCGEN05 0
#endif

// ============================================================================
// Helpers
// ============================================================================

__device__ __forceinline__ uint32_t elect_one_pred() {
    uint32_t pred;
    asm volatile(
        "{\n\t"
        ".reg .pred p;\n\t"
        "elect.sync _|p, 0xFFFFFFFF;\n\t"
        "selp.b32 %0, 1, 0, p;\n\t"
        "}"
        : "=r"(pred));
    return pred;
}

__device__ __forceinline__ uint32_t smem_to_u32(const void* smem_ptr) {
    uint32_t addr;
    asm("{ .reg .u64 tmp; cvta.to.shared.u64 tmp, %1; cvt.u32.u64 %0, tmp; }"
        : "=r"(addr) : "l"(smem_ptr));
    return addr;
}

__device__ __forceinline__ uint32_t cluster_ctarank_u32() {
    uint32_t r;
    asm("mov.u32 %0, %%cluster_ctarank;" : "=r"(r));
    return r;
}

#define MBARRIER_INIT(mbar, count) \
    asm volatile("mbarrier.init.shared.b64 [%0], %1;" \
                 :: "r"((uint32_t)(mbar)), "r"((uint32_t)(count)) : "memory")

#define MBARRIER_EXPECT_TX(mbar, tx_bytes) \
    asm volatile("mbarrier.arrive.expect_tx.shared.b64 _, [%0], %1;" \
                 :: "r"((uint32_t)(mbar)), "r"((uint32_t)(tx_bytes)) : "memory")

// Arrive on the leader CTA's copy of this barrier (clear bit 24).
#define MBARRIER_ARRIVE_LEADER(mbar) \
    asm volatile( \
        "{\n\t" \
        ".reg .b32 la;\n\t" \
        "and.b32 la, %0, 0xFEFFFFFF;\n\t" \
        "mbarrier.arrive.shared::cluster.b64 _, [la];\n\t" \
        "}" \
        :: "r"((uint32_t)(mbar)) : "memory")

#define MBARRIER_WAIT_PARITY(mbar, parity) do {                                  \
    uint32_t _mbar = (uint32_t)(mbar);                                           \
    uint32_t _par  = (uint32_t)(parity);                                         \
    asm volatile(                                                                \
        "{\n\t"                                                                  \
        ".reg .pred P1;\n\t"                                                     \
        "WAIT_LOOP_%=:\n\t"                                                      \
        "mbarrier.try_wait.parity.acquire.cta.shared::cta.b64 P1, [%0], %1, 0x989680;\n\t" \
        "@P1 bra.uni WAIT_DONE_%=;\n\t"                                          \
        "bra.uni WAIT_LOOP_%=;\n\t"                                              \
        "WAIT_DONE_%=:\n\t"                                                      \
        "}"                                                                      \
        :: "r"(_mbar), "r"(_par) : "memory");                                    \
} while (0)

#define MBARRIER_WAIT_PARITY_RELAXED(mbar, parity) do {                          \
    uint32_t _mbar = (uint32_t)(mbar);                                           \
    uint32_t _par  = (uint32_t)(parity);                                         \
    asm volatile(                                                                \
        "{\n\t"                                                                  \
        ".reg .pred P1;\n\t"                                                     \
        "WAIT_LOOP_%=:\n\t"                                                      \
        "mbarrier.try_wait.parity.relaxed.cta.shared::cta.b64 P1, [%0], %1, 0x989680;\n\t" \
        "@P1 bra.uni WAIT_DONE_%=;\n\t"                                          \
        "bra.uni WAIT_LOOP_%=;\n\t"                                              \
        "WAIT_DONE_%=:\n\t"                                                      \
        "}"                                                                      \
        :: "r"(_mbar), "r"(_par) : "memory");                                    \
} while (0)

// cg2 TMA load: both CTAs execute; complete_tx targets the LEADER CTA's barrier.
#define TMA_LOAD_3D_CG2(smem_addr, tensor_map, cx, cy, cz, mbar) \
    asm volatile( \
        "{\n\t" \
        ".reg .b32 leaderBar;\n\t" \
        "and.b32 leaderBar, %5, 0xFEFFFFFF;\n\t" \
        "cp.async.bulk.tensor.3d.cta_group::2.shared::cluster.global" \
        ".tile.mbarrier::complete_tx::bytes " \
        "[%0], [%1, {%2, %3, %4}], [leaderBar];\n\t" \
        "}" \
        :: "r"((uint32_t)(smem_addr)), "l"(tensor_map), \
           "r"((int32_t)(cx)), "r"((int32_t)(cy)), "r"((int32_t)(cz)), \
           "r"((uint32_t)(mbar)) \
        : "memory")

#define TCGEN05_ALLOC_CG2(smem_result_addr, nCols) \
    asm volatile("tcgen05.alloc.cta_group::2.sync.aligned.shared::cta.b32 [%0], %1;" \
                 :: "r"((uint32_t)(smem_result_addr)), "r"((uint32_t)(nCols)) : "memory")

#define TCGEN05_DEALLOC_CG2(tmem_addr, nCols) \
    asm volatile("tcgen05.dealloc.cta_group::2.sync.aligned.b32 %0, %1;" \
                 :: "r"(tmem_addr), "r"((uint32_t)(nCols)))

#define TCGEN05_RELINQUISH_ALLOC_PERMIT_CG2() \
    asm volatile("tcgen05.relinquish_alloc_permit.cta_group::2.sync.aligned;")

#define TCGEN05_COMMIT_MULTICAST_CG2(mbar, cta_mask) \
    asm volatile( \
        "tcgen05.commit.cta_group::2.mbarrier::arrive::one.shared::cluster.multicast::cluster.b64 [%0], %1;" \
        :: "r"((uint32_t)(mbar)), "h"((uint16_t)(cta_mask)) : "memory")

#define TCGEN05_FENCE_AFTER() \
    asm volatile("tcgen05.fence::after_thread_sync;" ::: "memory")

#define TCGEN05_FENCE_BEFORE() \
    asm volatile("tcgen05.fence::before_thread_sync;" ::: "memory")

#define TCGEN05_WAIT_LD() \
    asm volatile("tcgen05.wait::ld.sync.aligned;" ::: "memory")

#define CLUSTER_SYNC() do { \
    asm volatile("barrier.cluster.arrive.aligned;" ::: "memory"); \
    asm volatile("barrier.cluster.wait.aligned;" ::: "memory"); \
} while (0)

#define TCGEN05_LD_32X32B_X32(r, tmem_addr) \
    asm volatile( \
        "tcgen05.ld.sync.aligned.32x32b.x32.b32 " \
        "{%0, %1, %2, %3, %4, %5, %6, %7, " \
        " %8, %9, %10, %11, %12, %13, %14, %15, " \
        " %16, %17, %18, %19, %20, %21, %22, %23, " \
        " %24, %25, %26, %27, %28, %29, %30, %31}, [%32];" \
        : "=r"((r)[0]),  "=r"((r)[1]),  "=r"((r)[2]),  "=r"((r)[3]), \
          "=r"((r)[4]),  "=r"((r)[5]),  "=r"((r)[6]),  "=r"((r)[7]), \
          "=r"((r)[8]),  "=r"((r)[9]),  "=r"((r)[10]), "=r"((r)[11]), \
          "=r"((r)[12]), "=r"((r)[13]), "=r"((r)[14]), "=r"((r)[15]), \
          "=r"((r)[16]), "=r"((r)[17]), "=r"((r)[18]), "=r"((r)[19]), \
          "=r"((r)[20]), "=r"((r)[21]), "=r"((r)[22]), "=r"((r)[23]), \
          "=r"((r)[24]), "=r"((r)[25]), "=r"((r)[26]), "=r"((r)[27]), \
          "=r"((r)[28]), "=r"((r)[29]), "=r"((r)[30]), "=r"((r)[31]) \
        : "r"(tmem_addr))

// SW128 K-major SMEM descriptor (LBO=1, SBO=64, version=1, layout=SW128)
static constexpr uint64_t SMEM_DESC_BASE_SW128 =
    (uint64_t(2)  << 61)
    | (uint64_t(1) << 46)
    | (uint64_t(64) << 32)
    | (uint64_t(1) << 16);

#define MAKE_SMEM_DESC(base_addr) \
    (SMEM_DESC_BASE_SW128 | ((uint64_t)((base_addr) >> 4) & 0x3FFF))

#if HAS_TCGEN05
__device__ __forceinline__ void tcgen05_mma_f8_ss_cg2(
    uint32_t d_tmem, uint64_t a_desc, uint64_t b_desc, uint32_t idesc, bool acc)
{
    uint32_t en = acc ? 1u : 0u;
    asm volatile(
        "{\n\t"
        ".reg .pred p;\n\t"
        "setp.ne.u32 p, %5, 0;\n\t"
        "tcgen05.mma.cta_group::2.kind::f8f6f4 [%0], %1, %2, %3, "
        "{%4, %4, %4, %4, %4, %4, %4, %4}, p;\n\t"
        "}"
        :: "r"(d_tmem), "l"(a_desc), "l"(b_desc), "r"(idesc), "r"(0u), "r"(en)
        : "memory");
}
#endif

// ============================================================================
// Problem constants
// ============================================================================

static constexpr int M_TOT = 8192;      // B*S
static constexpr int K_TOT = 4096;
static constexpr int N_TOT = 16384;

static constexpr int TMP   = 256;       // M tile per CTA pair (128 per CTA)
static constexpr int TN    = 512;       // N tile per pair (2 x N=256 cg2 MMAs)
static constexpr int MMA_N = 256;
static constexpr int KC    = 128;       // K chunk (bytes == fp8 elements)
static constexpr int NCHUNK = K_TOT / KC;   // 32
static constexpr int NSTAGES = 4;

static constexpr int A_BYTES = 128 * KC;        // per-CTA A half
static constexpr int BSEG    = 128 * KC;        // per-CTA half of one N=256 atom
static constexpr int STAGE_BYTES = A_BYTES + 2 * BSEG;   // 49152 per CTA
static constexpr int PAIR_STAGE_TX = 2 * STAGE_BYTES;    // 98304

static constexpr int SMEM_TMEM  = 0;
static constexpr int SMEM_DONE  = 16;   // MMA->epilogue per-tile completion
static constexpr int SMEM_ACCF  = 24;   // epilogue->MMA accumulator-free (count=2)
static constexpr int SMEM_FULL0 = 32;   // full[s] = 32 + s*16, empty[s] = 40 + s*16
static constexpr int SMEM_TILE0 = 1024;
static constexpr int SMEM_TOTAL = SMEM_TILE0 + NSTAGES * STAGE_BYTES;  // 197632

static constexpr int TILES_MP = M_TOT / TMP;   // 32 m-pairs
static constexpr int TILES_NT = N_TOT / TN;    // 32 n-tiles
static constexpr int NTILES   = TILES_MP * TILES_NT;   // 1024
static constexpr int GROUP_MP = 8;             // raster grouping for L2 reuse

static constexpr int NSM       = 152;   // GB300 has 152 SMs
static constexpr int NCLUSTERS = NSM / 2;  // 76 persistent clusters

// idesc for cg2 kind::f8f6f4, e4m3 x e4m3 -> f32, M=256, N=256
static constexpr uint32_t MMA_IDESC_CG2 =
    (1u << 4) | ((uint32_t)(MMA_N / 8) << 17) | ((uint32_t)(TMP / 16) << 24);

// Scratch: quantized activations + canonical e4m3 weights
__device__ __align__(256) uint8_t g_Aq[(size_t)M_TOT * K_TOT];
__device__ __align__(256) uint8_t g_Wq[(size_t)N_TOT * K_TOT];
__device__ int g_wmode;   // 0 = raw fp8 bytes, 1 = float32 upcast, 2 = bf16 upcast

// Tile raster (shared by all roles): grouped for L2 reuse.
__device__ __forceinline__ void tile_coords(int t, int& m0, int& n0) {
    int group = t / (GROUP_MP * TILES_NT);
    int inner = t % (GROUP_MP * TILES_NT);
    int mt = group * GROUP_MP + (inner % GROUP_MP);
    int nt = inner / GROUP_MP;
    m0 = mt * TMP;
    n0 = nt * TN;
}

// ============================================================================
// Kernel 0: probe weight dtype (see R2 post-mortem).
// ============================================================================

__global__ void probe_kernel(const uint8_t* __restrict__ w)
{
    if (threadIdx.x != 0 || blockIdx.x != 0) return;
    const uint32_t* wu = reinterpret_cast<const uint32_t*>(w);
    bool is_f32 = true;
    for (int i = 0; i < 64; i++) {
        uint32_t b = wu[i];
        float v = __uint_as_float(b);
        bool ok = (fabsf(v) < 1.0f) && ((b & 0xFFFFFu) == 0u);
        if (!ok) { is_f32 = false; break; }
    }
    if (is_f32) { g_wmode = 1; return; }
    const uint16_t* wh = reinterpret_cast<const uint16_t*>(w);
    bool is_bf16 = true;
    for (int i = 0; i < 128; i++) {
        float v = __uint_as_float(((uint32_t)wh[i]) << 16);
        if (!(fabsf(v) < 1.0f)) { is_bf16 = false; break; }
    }
    g_wmode = is_bf16 ? 2 : 0;
}

// ============================================================================
// Kernel 1: materialize canonical e4m3 weight bytes in g_Wq
// ============================================================================

__global__ void __launch_bounds__(256) wquant_kernel(const uint8_t* __restrict__ w)
{
    int mode = g_wmode;
    const unsigned n16 = (unsigned)(((size_t)N_TOT * K_TOT) / 16u);
    uint4* __restrict__ ov = reinterpret_cast<uint4*>(g_Wq);
    unsigned stride = blockDim.x * gridDim.x;

    if (mode == 1) {
        const float4* __restrict__ wf = reinterpret_cast<const float4*>(w);
        for (unsigned i = blockIdx.x * blockDim.x + threadIdx.x; i < n16; i += stride) {
            unsigned r[4];
            #pragma unroll
            for (int j = 0; j < 4; j++) {
                float4 v = wf[(size_t)i * 4 + j];
                unsigned p0 = (unsigned)__nv_cvt_float2_to_fp8x2(
                    make_float2(v.x, v.y), __NV_SATFINITE, __NV_E4M3);
                unsigned p1 = (unsigned)__nv_cvt_float2_to_fp8x2(
                    make_float2(v.z, v.w), __NV_SATFINITE, __NV_E4M3);
                r[j] = p0 | (p1 << 16);
            }
            ov[i] = make_uint4(r[0], r[1], r[2], r[3]);
        }
    } else if (mode == 2) {
        const uint4* __restrict__ wb = reinterpret_cast<const uint4*>(w);
        for (unsigned i = blockIdx.x * blockDim.x + threadIdx.x; i < n16; i += stride) {
            unsigned r[4];
            #pragma unroll
            for (int half = 0; half < 2; half++) {
                uint4 v = wb[(size_t)i * 2 + half];
                unsigned u[4] = {v.x, v.y, v.z, v.w};
                #pragma unroll
                for (int j = 0; j < 2; j++) {
                    float2 f0, f1;
                    f0.x = __uint_as_float((u[j*2+0] & 0xFFFFu) << 16);
                    f0.y = __uint_as_float((u[j*2+0] >> 16) << 16);
                    f1.x = __uint_as_float((u[j*2+1] & 0xFFFFu) << 16);
                    f1.y = __uint_as_float((u[j*2+1] >> 16) << 16);
                    unsigned p0 = (unsigned)__nv_cvt_float2_to_fp8x2(f0, __NV_SATFINITE, __NV_E4M3);
                    unsigned p1 = (unsigned)__nv_cvt_float2_to_fp8x2(f1, __NV_SATFINITE, __NV_E4M3);
                    r[half*2 + j] = p0 | (p1 << 16);
                }
            }
            ov[i] = make_uint4(r[0], r[1], r[2], r[3]);
        }
    } else {
        const uint4* __restrict__ wb = reinterpret_cast<const uint4*>(w);
        for (unsigned i = blockIdx.x * blockDim.x + threadIdx.x; i < n16; i += stride) {
            ov[i] = wb[i];
        }
    }
}

// ============================================================================
// Kernel 2: quantize x (f32) -> e4m3 at x/input_scale
// ============================================================================

__global__ void __launch_bounds__(256) quant_kernel(
    const float* __restrict__ x, const float* __restrict__ s_in)
{
    float inv = 1.0f / __ldg(s_in);
    const unsigned n16 = (unsigned)(((size_t)M_TOT * K_TOT) / 16u);
    const float4* __restrict__ xv = reinterpret_cast<const float4*>(x);
    uint4* __restrict__ ov = reinterpret_cast<uint4*>(g_Aq);
    unsigned stride = blockDim.x * gridDim.x;
    for (unsigned i = blockIdx.x * blockDim.x + threadIdx.x; i < n16; i += stride) {
        unsigned r[4];
        #pragma unroll
        for (int j = 0; j < 4; j++) {
            float4 v = xv[(size_t)i * 4 + j];
            float2 lo = make_float2(v.x * inv, v.y * inv);
            float2 hi = make_float2(v.z * inv, v.w * inv);
            unsigned p0 = (unsigned)__nv_cvt_float2_to_fp8x2(lo, __NV_SATFINITE, __NV_E4M3);
            unsigned p1 = (unsigned)__nv_cvt_float2_to_fp8x2(hi, __NV_SATFINITE, __NV_E4M3);
            r[j] = p0 | (p1 << 16);
        }
        ov[i] = make_uint4(r[0], r[1], r[2], r[3]);
    }
}

// ============================================================================
// Kernel 3: persistent warp-specialized 2-CTA FP8 GEMM.
//   76 clusters x ~13 tiles each. Warps: 0-3 epilogue, 4 TMA producer,
//   5 MMA issuer (leader CTA). Stage ring runs continuously across tiles;
//   producer prefetches tile t+1 while epilogue drains tile t.
// ============================================================================

__global__ void __launch_bounds__(256, 1) __cluster_dims__(2, 1, 1)
fp8gemm_kernel(const __grid_constant__ CUtensorMap tma_a,
               const __grid_constant__ CUtensorMap tma_b,
               const float* __restrict__ bias,
               const float* __restrict__ s_in,
               const float* __restrict__ s_w,
               float* __restrict__ out)
{
    extern __shared__ char smem[];
    int tid = threadIdx.x;

#if HAS_TCGEN05
    uint32_t sb = smem_to_u32(smem);
    int wid = tid >> 5;
    int lid = tid & 31;
    uint32_t rank = cluster_ctarank_u32();
    int cid = blockIdx.x >> 1;   // cluster id, 0..NCLUSTERS-1

    if (wid == 4) TCGEN05_ALLOC_CG2(sb + SMEM_TMEM, 512);
    if (tid == 0) {
        MBARRIER_INIT(sb + SMEM_DONE, 1);
        MBARRIER_INIT(sb + SMEM_ACCF, 2);   // one arrive per CTA's epilogue
        #pragma unroll
        for (int s = 0; s < NSTAGES; s++) {
            MBARRIER_INIT(sb + SMEM_FULL0 + s * 16, 1);      // full[s] (leader)
            MBARRIER_INIT(sb + SMEM_FULL0 + s * 16 + 8, 1);  // empty[s] (per-CTA)
        }
        asm volatile("fence.mbarrier_init.release.cluster;" ::: "memory");
    }
    __syncthreads();
    CLUSTER_SYNC();

    uint32_t tmem;
    asm volatile("ld.shared.b32 %0, [%1];" : "=r"(tmem) : "r"(sb + SMEM_TMEM));

    if (wid == 4) {
        // ---- TMA producer (both CTAs; completes target leader full[s]) ----
        if (elect_one_pred()) {
            int stage = 0, phase = 1;   // fresh-barrier convention: parity-1 passes
            for (int t = cid; t < NTILES; t += NCLUSTERS) {
                int m0, n0; tile_coords(t, m0, n0);
                for (int c = 0; c < NCHUNK; c++) {
                    MBARRIER_WAIT_PARITY_RELAXED(sb + SMEM_FULL0 + stage * 16 + 8, phase);
                    if (rank == 0)
                        MBARRIER_EXPECT_TX(sb + SMEM_FULL0 + stage * 16, PAIR_STAGE_TX);
                    uint32_t dst = sb + SMEM_TILE0 + stage * STAGE_BYTES;
                    uint32_t fullbar = sb + SMEM_FULL0 + stage * 16;
                    TMA_LOAD_3D_CG2(dst, &tma_a, c * KC, m0 + (int)rank * 128, 0, fullbar);
                    TMA_LOAD_3D_CG2(dst + A_BYTES, &tma_b,
                                    c * KC, n0 + (int)rank * 128, 0, fullbar);
                    TMA_LOAD_3D_CG2(dst + A_BYTES + BSEG, &tma_b,
                                    c * KC, n0 + 256 + (int)rank * 128, 0, fullbar);
                    if (++stage == NSTAGES) { stage = 0; phase ^= 1; }
                }
            }
        }
    } else if (wid == 5 && rank == 0) {
        // ---- MMA issuer (leader only) ----
        if (elect_one_pred()) {
            int stage = 0, phase = 0;
            int accph = 1;              // fresh-barrier convention: first wait passes
            for (int t = cid; t < NTILES; t += NCLUSTERS) {
                // D must be free (previous tile's epilogue finished in BOTH CTAs)
                MBARRIER_WAIT_PARITY(sb + SMEM_ACCF, accph);
                accph ^= 1;
                TCGEN05_FENCE_AFTER();
                for (int c = 0; c < NCHUNK; c++) {
                    MBARRIER_WAIT_PARITY_RELAXED(sb + SMEM_FULL0 + stage * 16, phase);
                    uint32_t base = sb + SMEM_TILE0 + stage * STAGE_BYTES;
                    uint64_t ad  = MAKE_SMEM_DESC(base);
                    uint64_t bd0 = MAKE_SMEM_DESC(base + A_BYTES);
                    uint64_t bd1 = MAKE_SMEM_DESC(base + A_BYTES + BSEG);
                    #pragma unroll
                    for (int k = 0; k < KC / 32; k++) {
                        bool acc = !(c == 0 && k == 0);
                        tcgen05_mma_f8_ss_cg2(tmem,       ad + k * 2, bd0 + k * 2, MMA_IDESC_CG2, acc);
                        tcgen05_mma_f8_ss_cg2(tmem + 256, ad + k * 2, bd1 + k * 2, MMA_IDESC_CG2, acc);
                    }
                    TCGEN05_COMMIT_MULTICAST_CG2(sb + SMEM_FULL0 + stage * 16 + 8, 0x3);
                    if (++stage == NSTAGES) { stage = 0; phase ^= 1; }
                }
                // Tile complete -> wake epilogue in both CTAs
                TCGEN05_COMMIT_MULTICAST_CG2(sb + SMEM_DONE, 0x3);
            }
        }
    } else if (wid < 4) {
        // ---- Epilogue (warps 0-3 of both CTAs) ----
        float scale = __ldg(s_in) * __ldg(s_w);
        int row = wid * 32 + lid;                  // 0..127 (M within CTA half)
        int doneph = 0;
        for (int t = cid; t < NTILES; t += NCLUSTERS) {
            int m0, n0; tile_coords(t, m0, n0);
            MBARRIER_WAIT_PARITY(sb + SMEM_DONE, doneph);
            doneph ^= 1;
            TCGEN05_FENCE_AFTER();

            float* orow = out + (size_t)(m0 + (int)rank * 128 + row) * N_TOT + n0;
            #pragma unroll 1
            for (int nb = 0; nb < TN; nb += 32) {
                uint32_t r[32];
                TCGEN05_LD_32X32B_X32(r, tmem + nb);
                TCGEN05_WAIT_LD();
                #pragma unroll
                for (int j = 0; j < 32; j += 4) {
                    float4 bv = *reinterpret_cast<const float4*>(bias + n0 + nb + j);
                    float4 o;
                    o.x = __uint_as_float(r[j + 0]) * scale + bv.x;
                    o.y = __uint_as_float(r[j + 1]) * scale + bv.y;
                    o.z = __uint_as_float(r[j + 2]) * scale + bv.z;
                    o.w = __uint_as_float(r[j + 3]) * scale + bv.w;
                    *reinterpret_cast<float4*>(orow + nb + j) = o;
                }
            }
            TCGEN05_FENCE_BEFORE();
            // All 4 epilogue warps of this CTA done -> one arrive on leader ACCF
            asm volatile("bar.sync 1, 128;" ::: "memory");
            if (tid == 0) MBARRIER_ARRIVE_LEADER(sb + SMEM_ACCF);
        }
    }

    __syncthreads();
    if (wid == 4) {
        TCGEN05_RELINQUISH_ALLOC_PERMIT_CG2();
        TCGEN05_DEALLOC_CG2(tmem, 512);
    }
    CLUSTER_SYNC();
#else
    // ------------------------------------------------------------------
    // Fallback for PTX passes without tcgen05 (plain compute_103).
    // Persistent loop over the same tile raster; slow but correct.
    // ------------------------------------------------------------------
    int cid  = blockIdx.x >> 1;
    int rank = blockIdx.x & 1;
    float*   lut   = reinterpret_cast<float*>(smem);
    uint8_t* wtile = reinterpret_cast<uint8_t*>(smem + 1024);
    uint8_t* atile = reinterpret_cast<uint8_t*>(smem + 1024 + 64 * KC);

    for (int i = tid; i < 256; i += 256) {
        __half_raw hr = __nv_cvt_fp8_to_halfraw((__nv_fp8_storage_t)i, __NV_E4M3);
        lut[i] = __half2float(*reinterpret_cast<__half*>(&hr));
    }
    __syncthreads();

    float scale = __ldg(s_in) * __ldg(s_w);

    for (int t = cid; t < NTILES; t += NCLUSTERS) {
        int m0, n0; tile_coords(t, m0, n0);
        int row = m0 + rank * 128 + (tid & 127);
        int half = tid >> 7;   // 2 x 128-thread groups split the TN range

        for (int cb = half * (TN / 128); cb < (half + 1) * (TN / 128); cb++) {
            int nb = n0 + cb * 64;
            float acc[64];
            #pragma unroll
            for (int j = 0; j < 64; j++) acc[j] = 0.0f;

            for (int c = 0; c < NCHUNK; c++) {
                __syncthreads();
                for (int idx = tid; idx < 64 * (KC / 4); idx += 256) {
                    int r = idx / (KC / 4), j = idx % (KC / 4);
                    reinterpret_cast<uint32_t*>(wtile)[idx] =
                        reinterpret_cast<const uint32_t*>(g_Wq + (size_t)(nb + r) * K_TOT + c * KC)[j];
                }
                if (half == 0) {
                    for (int j = 0; j < KC / 4; j++) {
                        reinterpret_cast<uint32_t*>(atile)[(tid & 127) * (KC / 4) + j] =
                            reinterpret_cast<const uint32_t*>(g_Aq + (size_t)row * K_TOT + c * KC)[j];
                    }
                }
                __syncthreads();

                for (int n = 0; n < 64; n++) {
                    float s = 0.0f;
                    const uint32_t* wr = reinterpret_cast<const uint32_t*>(wtile + n * KC);
                    const uint32_t* ar = reinterpret_cast<const uint32_t*>(atile + (tid & 127) * KC);
                    for (int k4 = 0; k4 < KC / 4; k4++) {
                        uint32_t av = ar[k4], wv = wr[k4];
                        s += lut[av & 0xFF]         * lut[wv & 0xFF];
                        s += lut[(av >> 8) & 0xFF]  * lut[(wv >> 8) & 0xFF];
                        s += lut[(av >> 16) & 0xFF] * lut[(wv >> 16) & 0xFF];
                        s += lut[(av >> 24) & 0xFF] * lut[(wv >> 24) & 0xFF];
                    }
                    acc[n] += s;
                }
            }

            float* orow = out + (size_t)row * N_TOT + nb;
            for (int n = 0; n < 64; n++)
                orow[n] = acc[n] * scale + __ldg(bias + nb + n);
            __syncthreads();
        }
    }
#endif
}

// ============================================================================
// Host launch
// ============================================================================

typedef CUresult (*cuTensorMapEncodeTiled_t)(
    CUtensorMap*, CUtensorMapDataType, cuuint32_t, void*,
    const cuuint64_t*, const cuuint64_t*, const cuuint32_t*, const cuuint32_t*,
    CUtensorMapInterleave, CUtensorMapSwizzle, CUtensorMapL2promotion,
    CUtensorMapFloatOOBfill);

static cuTensorMapEncodeTiled_t get_encode_fn() {
    void* fn = nullptr;
    cudaDriverEntryPointQueryResult st;
#if CUDART_VERSION >= 12050
    cudaGetDriverEntryPointByVersion("cuTensorMapEncodeTiled", &fn, 12000,
                                     cudaEnableDefault, &st);
#else
    cudaGetDriverEntryPoint("cuTensorMapEncodeTiled", &fn, cudaEnableDefault, &st);
#endif
    return (cuTensorMapEncodeTiled_t)fn;
}

static void encode_fp8_map(cuTensorMapEncodeTiled_t enc, CUtensorMap* out_map,
                           void* base, uint64_t rows) {
    uint64_t dims[3]    = {(uint64_t)K_TOT, rows, 1};
    uint64_t strides[2] = {(uint64_t)K_TOT, (uint64_t)K_TOT * rows};
    uint32_t box[3]     = {(uint32_t)KC, 128, 1};
    uint32_t estr[3]    = {1, 1, 1};
    enc(out_map, CU_TENSOR_MAP_DATA_TYPE_UINT8, 3, base,
        dims, strides, box, estr,
        CU_TENSOR_MAP_INTERLEAVE_NONE, CU_TENSOR_MAP_SWIZZLE_128B,
        CU_TENSOR_MAP_L2_PROMOTION_L2_128B, CU_TENSOR_MAP_FLOAT_OOB_FILL_NONE);
}

extern "C" void kernel_launch(void* const* d_in, const int* in_sizes, int n_in,
                              void* d_out, int out_size) {
    const float* x    = (const float*)d_in[0];
    const uint8_t* w  = (const uint8_t*)d_in[1];  // fp8 weights (raw / f32 / bf16)
    const float* bias = (const float*)d_in[2];
    const float* s_in = (const float*)d_in[3];
    const float* s_w  = (const float*)d_in[4];
    float* out        = (float*)d_out;

    probe_kernel<<<1, 32>>>(w);
    wquant_kernel<<<4096, 256>>>(w);
    quant_kernel<<<2048, 256>>>(x, s_in);

    void* aq_ptr = nullptr;
    void* wq_ptr = nullptr;
    cudaGetSymbolAddress(&aq_ptr, g_Aq);
    cudaGetSymbolAddress(&wq_ptr, g_Wq);
    cuTensorMapEncodeTiled_t enc = get_encode_fn();
    CUtensorMap tma_a, tma_b;
    encode_fp8_map(enc, &tma_a, aq_ptr, (uint64_t)M_TOT);
    encode_fp8_map(enc, &tma_b, wq_ptr, (uint64_t)N_TOT);

    cudaFuncSetAttribute(fp8gemm_kernel,
                         cudaFuncAttributeMaxDynamicSharedMemorySize, SMEM_TOTAL);
    fp8gemm_kernel<<<NSM, 256, SMEM_TOTAL>>>(
        tma_a, tma_b, bias, s_in, s_w, out);
}

// round 6
// speedup vs baseline: 1.2993x; 1.0386x over previous
#include <cuda_runtime.h>
#include <cuda.h>
#include <cuda_fp8.h>
#include <cuda_fp16.h>
#include <cuda_bf16.h>
#include <cstdint>
#include <cstdio>

// ============================================================================
// Arch-feature gate (see R1 post-mortem).
// ============================================================================
#if defined(__CUDA_ARCH__) && \
    (defined(__CUDA_ARCH_FEAT_SM103_ALL) || defined(__CUDA_ARCH_FEAT_SM100_ALL) || \
     defined(__CUDA_ARCH_SPECIFIC__) || defined(__CUDA_ARCH_FAMILY_SPECIFIC__))
#define HAS_TCGEN05 1
#else
#define HAS_TCGEN05 0
#endif

// ============================================================================
// Helpers
// ============================================================================

__device__ __forceinline__ uint32_t elect_one_pred() {
    uint32_t pred;
    asm volatile(
        "{\n\t"
        ".reg .pred p;\n\t"
        "elect.sync _|p, 0xFFFFFFFF;\n\t"
        "selp.b32 %0, 1, 0, p;\n\t"
        "}"
        : "=r"(pred));
    return pred;
}

__device__ __forceinline__ uint32_t smem_to_u32(const void* smem_ptr) {
    uint32_t addr;
    asm("{ .reg .u64 tmp; cvta.to.shared.u64 tmp, %1; cvt.u32.u64 %0, tmp; }"
        : "=r"(addr) : "l"(smem_ptr));
    return addr;
}

__device__ __forceinline__ uint32_t cluster_ctarank_u32() {
    uint32_t r;
    asm("mov.u32 %0, %%cluster_ctarank;" : "=r"(r));
    return r;
}

#define MBARRIER_INIT(mbar, count) \
    asm volatile("mbarrier.init.shared.b64 [%0], %1;" \
                 :: "r"((uint32_t)(mbar)), "r"((uint32_t)(count)) : "memory")

#define MBARRIER_EXPECT_TX(mbar, tx_bytes) \
    asm volatile("mbarrier.arrive.expect_tx.shared.b64 _, [%0], %1;" \
                 :: "r"((uint32_t)(mbar)), "r"((uint32_t)(tx_bytes)) : "memory")

// Arrive on the leader CTA's copy of this barrier (clear bit 24).
#define MBARRIER_ARRIVE_LEADER(mbar) \
    asm volatile( \
        "{\n\t" \
        ".reg .b32 la;\n\t" \
        "and.b32 la, %0, 0xFEFFFFFF;\n\t" \
        "mbarrier.arrive.shared::cluster.b64 _, [la];\n\t" \
        "}" \
        :: "r"((uint32_t)(mbar)) : "memory")

#define MBARRIER_WAIT_PARITY(mbar, parity) do {                                  \
    uint32_t _mbar = (uint32_t)(mbar);                                           \
    uint32_t _par  = (uint32_t)(parity);                                         \
    asm volatile(                                                                \
        "{\n\t"                                                                  \
        ".reg .pred P1;\n\t"                                                     \
        "WAIT_LOOP_%=:\n\t"                                                      \
        "mbarrier.try_wait.parity.acquire.cta.shared::cta.b64 P1, [%0], %1, 0x989680;\n\t" \
        "@P1 bra.uni WAIT_DONE_%=;\n\t"                                          \
        "bra.uni WAIT_LOOP_%=;\n\t"                                              \
        "WAIT_DONE_%=:\n\t"                                                      \
        "}"                                                                      \
        :: "r"(_mbar), "r"(_par) : "memory");                                    \
} while (0)

#define MBARRIER_WAIT_PARITY_RELAXED(mbar, parity) do {                          \
    uint32_t _mbar = (uint32_t)(mbar);                                           \
    uint32_t _par  = (uint32_t)(parity);                                         \
    asm volatile(                                                                \
        "{\n\t"                                                                  \
        ".reg .pred P1;\n\t"                                                     \
        "WAIT_LOOP_%=:\n\t"                                                      \
        "mbarrier.try_wait.parity.relaxed.cta.shared::cta.b64 P1, [%0], %1, 0x989680;\n\t" \
        "@P1 bra.uni WAIT_DONE_%=;\n\t"                                          \
        "bra.uni WAIT_LOOP_%=;\n\t"                                              \
        "WAIT_DONE_%=:\n\t"                                                      \
        "}"                                                                      \
        :: "r"(_mbar), "r"(_par) : "memory");                                    \
} while (0)

// cg2 TMA load: both CTAs execute; complete_tx targets the LEADER CTA's barrier.
#define TMA_LOAD_3D_CG2(smem_addr, tensor_map, cx, cy, cz, mbar) \
    asm volatile( \
        "{\n\t" \
        ".reg .b32 leaderBar;\n\t" \
        "and.b32 leaderBar, %5, 0xFEFFFFFF;\n\t" \
        "cp.async.bulk.tensor.3d.cta_group::2.shared::cluster.global" \
        ".tile.mbarrier::complete_tx::bytes " \
        "[%0], [%1, {%2, %3, %4}], [leaderBar];\n\t" \
        "}" \
        :: "r"((uint32_t)(smem_addr)), "l"(tensor_map), \
           "r"((int32_t)(cx)), "r"((int32_t)(cy)), "r"((int32_t)(cz)), \
           "r"((uint32_t)(mbar)) \
        : "memory")

#define TCGEN05_ALLOC_CG2(smem_result_addr, nCols) \
    asm volatile("tcgen05.alloc.cta_group::2.sync.aligned.shared::cta.b32 [%0], %1;" \
                 :: "r"((uint32_t)(smem_result_addr)), "r"((uint32_t)(nCols)) : "memory")

#define TCGEN05_DEALLOC_CG2(tmem_addr, nCols) \
    asm volatile("tcgen05.dealloc.cta_group::2.sync.aligned.b32 %0, %1;" \
                 :: "r"(tmem_addr), "r"((uint32_t)(nCols)))

#define TCGEN05_RELINQUISH_ALLOC_PERMIT_CG2() \
    asm volatile("tcgen05.relinquish_alloc_permit.cta_group::2.sync.aligned;")

#define TCGEN05_COMMIT_MULTICAST_CG2(mbar, cta_mask) \
    asm volatile( \
        "tcgen05.commit.cta_group::2.mbarrier::arrive::one.shared::cluster.multicast::cluster.b64 [%0], %1;" \
        :: "r"((uint32_t)(mbar)), "h"((uint16_t)(cta_mask)) : "memory")

#define TCGEN05_FENCE_AFTER() \
    asm volatile("tcgen05.fence::after_thread_sync;" ::: "memory")

#define TCGEN05_FENCE_BEFORE() \
    asm volatile("tcgen05.fence::before_thread_sync;" ::: "memory")

#define TCGEN05_WAIT_LD() \
    asm volatile("tcgen05.wait::ld.sync.aligned;" ::: "memory")

#define CLUSTER_SYNC() do { \
    asm volatile("barrier.cluster.arrive.aligned;" ::: "memory"); \
    asm volatile("barrier.cluster.wait.aligned;" ::: "memory"); \
} while (0)

#define TCGEN05_LD_32X32B_X32(r, tmem_addr) \
    asm volatile( \
        "tcgen05.ld.sync.aligned.32x32b.x32.b32 " \
        "{%0, %1, %2, %3, %4, %5, %6, %7, " \
        " %8, %9, %10, %11, %12, %13, %14, %15, " \
        " %16, %17, %18, %19, %20, %21, %22, %23, " \
        " %24, %25, %26, %27, %28, %29, %30, %31}, [%32];" \
        : "=r"((r)[0]),  "=r"((r)[1]),  "=r"((r)[2]),  "=r"((r)[3]), \
          "=r"((r)[4]),  "=r"((r)[5]),  "=r"((r)[6]),  "=r"((r)[7]), \
          "=r"((r)[8]),  "=r"((r)[9]),  "=r"((r)[10]), "=r"((r)[11]), \
          "=r"((r)[12]), "=r"((r)[13]), "=r"((r)[14]), "=r"((r)[15]), \
          "=r"((r)[16]), "=r"((r)[17]), "=r"((r)[18]), "=r"((r)[19]), \
          "=r"((r)[20]), "=r"((r)[21]), "=r"((r)[22]), "=r"((r)[23]), \
          "=r"((r)[24]), "=r"((r)[25]), "=r"((r)[26]), "=r"((r)[27]), \
          "=r"((r)[28]), "=r"((r)[29]), "=r"((r)[30]), "=r"((r)[31]) \
        : "r"(tmem_addr))

// SW128 K-major SMEM descriptor (LBO=1, SBO=64, version=1, layout=SW128)
static constexpr uint64_t SMEM_DESC_BASE_SW128 =
    (uint64_t(2)  << 61)
    | (uint64_t(1) << 46)
    | (uint64_t(64) << 32)
    | (uint64_t(1) << 16);

#define MAKE_SMEM_DESC(base_addr) \
    (SMEM_DESC_BASE_SW128 | ((uint64_t)((base_addr) >> 4) & 0x3FFF))

#if HAS_TCGEN05
__device__ __forceinline__ void tcgen05_mma_f8_ss_cg2(
    uint32_t d_tmem, uint64_t a_desc, uint64_t b_desc, uint32_t idesc, bool acc)
{
    uint32_t en = acc ? 1u : 0u;
    asm volatile(
        "{\n\t"
        ".reg .pred p;\n\t"
        "setp.ne.u32 p, %5, 0;\n\t"
        "tcgen05.mma.cta_group::2.kind::f8f6f4 [%0], %1, %2, %3, "
        "{%4, %4, %4, %4, %4, %4, %4, %4}, p;\n\t"
        "}"
        :: "r"(d_tmem), "l"(a_desc), "l"(b_desc), "r"(idesc), "r"(0u), "r"(en)
        : "memory");
}
#endif

// ============================================================================
// Problem constants
// ============================================================================

static constexpr int M_TOT = 8192;      // B*S
static constexpr int K_TOT = 4096;
static constexpr int N_TOT = 16384;

static constexpr int TMP   = 256;       // M tile per CTA pair (128 per CTA)
static constexpr int TN    = 512;       // N tile per pair (2 x N=256 cg2 MMAs)
static constexpr int MMA_N = 256;
static constexpr int KC    = 128;       // K chunk (bytes == fp8 elements)
static constexpr int NCHUNK = K_TOT / KC;   // 32
static constexpr int NSTAGES = 4;
static constexpr int RUNWAY  = NSTAGES; // chunks of MMA0-only issued before ACCF1

static constexpr int A_BYTES = 128 * KC;        // per-CTA A half
static constexpr int BSEG    = 128 * KC;        // per-CTA half of one N=256 atom
static constexpr int STAGE_BYTES = A_BYTES + 2 * BSEG;   // 49152 per CTA
static constexpr int PAIR_STAGE_TX = 2 * STAGE_BYTES;    // 98304

// SMEM layout
static constexpr int SMEM_TMEM  = 0;
static constexpr int SMEM_DONE  = 16;   // MMA->epilogue per-tile completion
static constexpr int SMEM_ACCF0 = 24;   // epilogue->MMA: buf0 free (count=2)
static constexpr int SMEM_FULL0 = 32;   // full[s]=32+s*16, empty[s]=40+s*16 (4 stages)
static constexpr int SMEM_ACCF1 = 96;   // epilogue->MMA: buf1 free (count=2)
static constexpr int SMEM_BIAS  = 1024; // 512 floats (2 KB)
static constexpr int SMEM_TILE0 = 3072; // 1024-aligned tile stages
static constexpr int SMEM_TOTAL = SMEM_TILE0 + NSTAGES * STAGE_BYTES;  // 199680

static constexpr int TILES_MP = M_TOT / TMP;   // 32 m-pairs
static constexpr int TILES_NT = N_TOT / TN;    // 32 n-tiles
static constexpr int NTILES   = TILES_MP * TILES_NT;   // 1024
static constexpr int GROUP_MP = 8;             // raster grouping for L2 reuse

static constexpr int NSM       = 152;   // GB300
static constexpr int NCLUSTERS = NSM / 2;  // 76 persistent clusters

// idesc for cg2 kind::f8f6f4, e4m3 x e4m3 -> f32, M=256, N=256
static constexpr uint32_t MMA_IDESC_CG2 =
    (1u << 4) | ((uint32_t)(MMA_N / 8) << 17) | ((uint32_t)(TMP / 16) << 24);

// Scratch: quantized activations + canonical e4m3 weights
__device__ __align__(256) uint8_t g_Aq[(size_t)M_TOT * K_TOT];
__device__ __align__(256) uint8_t g_Wq[(size_t)N_TOT * K_TOT];
__device__ int g_wmode;   // 0 = raw fp8 bytes, 1 = float32 upcast, 2 = bf16 upcast

// Tile raster (shared by all roles): grouped for L2 reuse.
__device__ __forceinline__ void tile_coords(int t, int& m0, int& n0) {
    int group = t / (GROUP_MP * TILES_NT);
    int inner = t % (GROUP_MP * TILES_NT);
    int mt = group * GROUP_MP + (inner % GROUP_MP);
    int nt = inner / GROUP_MP;
    m0 = mt * TMP;
    n0 = nt * TN;
}

// ============================================================================
// Kernel 0: probe weight dtype (see R2 post-mortem).
// ============================================================================

__global__ void probe_kernel(const uint8_t* __restrict__ w)
{
    if (threadIdx.x != 0 || blockIdx.x != 0) return;
    const uint32_t* wu = reinterpret_cast<const uint32_t*>(w);
    bool is_f32 = true;
    for (int i = 0; i < 64; i++) {
        uint32_t b = wu[i];
        float v = __uint_as_float(b);
        bool ok = (fabsf(v) < 1.0f) && ((b & 0xFFFFFu) == 0u);
        if (!ok) { is_f32 = false; break; }
    }
    if (is_f32) { g_wmode = 1; return; }
    const uint16_t* wh = reinterpret_cast<const uint16_t*>(w);
    bool is_bf16 = true;
    for (int i = 0; i < 128; i++) {
        float v = __uint_as_float(((uint32_t)wh[i]) << 16);
        if (!(fabsf(v) < 1.0f)) { is_bf16 = false; break; }
    }
    g_wmode = is_bf16 ? 2 : 0;
}

// ============================================================================
// Kernel 1: materialize canonical e4m3 weight bytes in g_Wq
// ============================================================================

__global__ void __launch_bounds__(256) wquant_kernel(const uint8_t* __restrict__ w)
{
    int mode = g_wmode;
    const unsigned n16 = (unsigned)(((size_t)N_TOT * K_TOT) / 16u);
    uint4* __restrict__ ov = reinterpret_cast<uint4*>(g_Wq);
    unsigned stride = blockDim.x * gridDim.x;

    if (mode == 1) {
        const float4* __restrict__ wf = reinterpret_cast<const float4*>(w);
        for (unsigned i = blockIdx.x * blockDim.x + threadIdx.x; i < n16; i += stride) {
            unsigned r[4];
            #pragma unroll
            for (int j = 0; j < 4; j++) {
                float4 v = wf[(size_t)i * 4 + j];
                unsigned p0 = (unsigned)__nv_cvt_float2_to_fp8x2(
                    make_float2(v.x, v.y), __NV_SATFINITE, __NV_E4M3);
                unsigned p1 = (unsigned)__nv_cvt_float2_to_fp8x2(
                    make_float2(v.z, v.w), __NV_SATFINITE, __NV_E4M3);
                r[j] = p0 | (p1 << 16);
            }
            ov[i] = make_uint4(r[0], r[1], r[2], r[3]);
        }
    } else if (mode == 2) {
        const uint4* __restrict__ wb = reinterpret_cast<const uint4*>(w);
        for (unsigned i = blockIdx.x * blockDim.x + threadIdx.x; i < n16; i += stride) {
            unsigned r[4];
            #pragma unroll
            for (int half = 0; half < 2; half++) {
                uint4 v = wb[(size_t)i * 2 + half];
                unsigned u[4] = {v.x, v.y, v.z, v.w};
                #pragma unroll
                for (int j = 0; j < 2; j++) {
                    float2 f0, f1;
                    f0.x = __uint_as_float((u[j*2+0] & 0xFFFFu) << 16);
                    f0.y = __uint_as_float((u[j*2+0] >> 16) << 16);
                    f1.x = __uint_as_float((u[j*2+1] & 0xFFFFu) << 16);
                    f1.y = __uint_as_float((u[j*2+1] >> 16) << 16);
                    unsigned p0 = (unsigned)__nv_cvt_float2_to_fp8x2(f0, __NV_SATFINITE, __NV_E4M3);
                    unsigned p1 = (unsigned)__nv_cvt_float2_to_fp8x2(f1, __NV_SATFINITE, __NV_E4M3);
                    r[half*2 + j] = p0 | (p1 << 16);
                }
            }
            ov[i] = make_uint4(r[0], r[1], r[2], r[3]);
        }
    } else {
        const uint4* __restrict__ wb = reinterpret_cast<const uint4*>(w);
        for (unsigned i = blockIdx.x * blockDim.x + threadIdx.x; i < n16; i += stride) {
            ov[i] = wb[i];
        }
    }
}

// ============================================================================
// Kernel 2: quantize x (f32) -> e4m3 at x/input_scale
// ============================================================================

__global__ void __launch_bounds__(256) quant_kernel(
    const float* __restrict__ x, const float* __restrict__ s_in)
{
    float inv = 1.0f / __ldg(s_in);
    const unsigned n16 = (unsigned)(((size_t)M_TOT * K_TOT) / 16u);
    const float4* __restrict__ xv = reinterpret_cast<const float4*>(x);
    uint4* __restrict__ ov = reinterpret_cast<uint4*>(g_Aq);
    unsigned stride = blockDim.x * gridDim.x;
    for (unsigned i = blockIdx.x * blockDim.x + threadIdx.x; i < n16; i += stride) {
        unsigned r[4];
        #pragma unroll
        for (int j = 0; j < 4; j++) {
            float4 v = xv[(size_t)i * 4 + j];
            float2 lo = make_float2(v.x * inv, v.y * inv);
            float2 hi = make_float2(v.z * inv, v.w * inv);
            unsigned p0 = (unsigned)__nv_cvt_float2_to_fp8x2(lo, __NV_SATFINITE, __NV_E4M3);
            unsigned p1 = (unsigned)__nv_cvt_float2_to_fp8x2(hi, __NV_SATFINITE, __NV_E4M3);
            r[j] = p0 | (p1 << 16);
        }
        ov[i] = make_uint4(r[0], r[1], r[2], r[3]);
    }
}

// ============================================================================
// Kernel 3: persistent warp-specialized 2-CTA FP8 GEMM, split accumulator.
//   buf0 = TMEM cols [0,256), buf1 = [256,512). Epilogue drains buf0, signals
//   ACCF0, drains buf1, signals ACCF1. MMA issuer starts the next tile's buf0
//   MMAs (runway of NSTAGES chunks, stages held) while buf1 is still draining.
// ============================================================================

__global__ void __launch_bounds__(256, 1) __cluster_dims__(2, 1, 1)
fp8gemm_kernel(const __grid_constant__ CUtensorMap tma_a,
               const __grid_constant__ CUtensorMap tma_b,
               const float* __restrict__ bias,
               const float* __restrict__ s_in,
               const float* __restrict__ s_w,
               float* __restrict__ out)
{
    extern __shared__ char smem[];
    int tid = threadIdx.x;

#if HAS_TCGEN05
    uint32_t sb = smem_to_u32(smem);
    int wid = tid >> 5;
    int lid = tid & 31;
    uint32_t rank = cluster_ctarank_u32();
    int cid = blockIdx.x >> 1;

    if (wid == 4) TCGEN05_ALLOC_CG2(sb + SMEM_TMEM, 512);
    if (tid == 0) {
        MBARRIER_INIT(sb + SMEM_DONE, 1);
        MBARRIER_INIT(sb + SMEM_ACCF0, 2);
        MBARRIER_INIT(sb + SMEM_ACCF1, 2);
        #pragma unroll
        for (int s = 0; s < NSTAGES; s++) {
            MBARRIER_INIT(sb + SMEM_FULL0 + s * 16, 1);      // full[s] (leader)
            MBARRIER_INIT(sb + SMEM_FULL0 + s * 16 + 8, 1);  // empty[s] (per-CTA)
        }
        asm volatile("fence.mbarrier_init.release.cluster;" ::: "memory");
    }
    __syncthreads();
    CLUSTER_SYNC();

    uint32_t tmem;
    asm volatile("ld.shared.b32 %0, [%1];" : "=r"(tmem) : "r"(sb + SMEM_TMEM));

    if (wid == 4) {
        // ---- TMA producer (both CTAs; completes target leader full[s]) ----
        if (elect_one_pred()) {
            int stage = 0, phase = 1;
            for (int t = cid; t < NTILES; t += NCLUSTERS) {
                int m0, n0; tile_coords(t, m0, n0);
                for (int c = 0; c < NCHUNK; c++) {
                    MBARRIER_WAIT_PARITY_RELAXED(sb + SMEM_FULL0 + stage * 16 + 8, phase);
                    if (rank == 0)
                        MBARRIER_EXPECT_TX(sb + SMEM_FULL0 + stage * 16, PAIR_STAGE_TX);
                    uint32_t dst = sb + SMEM_TILE0 + stage * STAGE_BYTES;
                    uint32_t fullbar = sb + SMEM_FULL0 + stage * 16;
                    TMA_LOAD_3D_CG2(dst, &tma_a, c * KC, m0 + (int)rank * 128, 0, fullbar);
                    TMA_LOAD_3D_CG2(dst + A_BYTES, &tma_b,
                                    c * KC, n0 + (int)rank * 128, 0, fullbar);
                    TMA_LOAD_3D_CG2(dst + A_BYTES + BSEG, &tma_b,
                                    c * KC, n0 + 256 + (int)rank * 128, 0, fullbar);
                    if (++stage == NSTAGES) { stage = 0; phase ^= 1; }
                }
            }
        }
    } else if (wid == 5 && rank == 0) {
        // ---- MMA issuer (leader only), runway-scheduled split accumulator ----
        if (elect_one_pred()) {
            int stage = 0, phase = 0;
            int ph0 = 1, ph1 = 1;       // fresh-barrier convention
            int held[RUNWAY];
            for (int t = cid; t < NTILES; t += NCLUSTERS) {
                MBARRIER_WAIT_PARITY(sb + SMEM_ACCF0, ph0);
                ph0 ^= 1;
                TCGEN05_FENCE_AFTER();
                for (int c = 0; c < NCHUNK; c++) {
                    MBARRIER_WAIT_PARITY_RELAXED(sb + SMEM_FULL0 + stage * 16, phase);
                    uint32_t base = sb + SMEM_TILE0 + stage * STAGE_BYTES;
                    uint64_t ad  = MAKE_SMEM_DESC(base);
                    uint64_t bd0 = MAKE_SMEM_DESC(base + A_BYTES);
                    #pragma unroll
                    for (int k = 0; k < KC / 32; k++)
                        tcgen05_mma_f8_ss_cg2(tmem, ad + k * 2, bd0 + k * 2,
                                              MMA_IDESC_CG2, !(c == 0 && k == 0));
                    if (c < RUNWAY) {
                        held[c] = stage;            // defer MMA1 + stage release
                    } else {
                        uint64_t bd1 = MAKE_SMEM_DESC(base + A_BYTES + BSEG);
                        #pragma unroll
                        for (int k = 0; k < KC / 32; k++)
                            tcgen05_mma_f8_ss_cg2(tmem + 256, ad + k * 2, bd1 + k * 2,
                                                  MMA_IDESC_CG2, true);
                        TCGEN05_COMMIT_MULTICAST_CG2(sb + SMEM_FULL0 + stage * 16 + 8, 0x3);
                    }
                    if (c == RUNWAY - 1) {
                        // buf1 must be free before its first write this tile
                        MBARRIER_WAIT_PARITY(sb + SMEM_ACCF1, ph1);
                        ph1 ^= 1;
                        TCGEN05_FENCE_AFTER();
                        #pragma unroll
                        for (int r = 0; r < RUNWAY; r++) {
                            uint32_t hb = sb + SMEM_TILE0 + held[r] * STAGE_BYTES;
                            uint64_t had = MAKE_SMEM_DESC(hb);
                            uint64_t hbd = MAKE_SMEM_DESC(hb + A_BYTES + BSEG);
                            #pragma unroll
                            for (int k = 0; k < KC / 32; k++)
                                tcgen05_mma_f8_ss_cg2(tmem + 256, had + k * 2, hbd + k * 2,
                                                      MMA_IDESC_CG2, !(r == 0 && k == 0));
                            TCGEN05_COMMIT_MULTICAST_CG2(sb + SMEM_FULL0 + held[r] * 16 + 8, 0x3);
                        }
                    }
                    if (++stage == NSTAGES) { stage = 0; phase ^= 1; }
                }
                TCGEN05_COMMIT_MULTICAST_CG2(sb + SMEM_DONE, 0x3);
            }
        }
    } else if (wid < 4) {
        // ---- Epilogue (warps 0-3 of both CTAs) ----
        float scale = __ldg(s_in) * __ldg(s_w);
        int row = wid * 32 + lid;                  // 0..127 (M within CTA half)
        int doneph = 0;
        float4* sbias = reinterpret_cast<float4*>(smem + SMEM_BIAS);
        for (int t = cid; t < NTILES; t += NCLUSTERS) {
            int m0, n0; tile_coords(t, m0, n0);
            // Preload bias for this tile (overlaps with the MMA phase)
            sbias[tid] = *reinterpret_cast<const float4*>(bias + n0 + tid * 4);
            asm volatile("bar.sync 1, 128;" ::: "memory");

            MBARRIER_WAIT_PARITY(sb + SMEM_DONE, doneph);
            doneph ^= 1;
            TCGEN05_FENCE_AFTER();

            float* orow = out + (size_t)(m0 + (int)rank * 128 + row) * N_TOT + n0;
            // ---- drain buf0 (cols 0..255) ----
            #pragma unroll 1
            for (int nb = 0; nb < 256; nb += 64) {
                uint32_t r[64];
                TCGEN05_LD_32X32B_X32(r, tmem + nb);
                TCGEN05_LD_32X32B_X32(r + 32, tmem + nb + 32);
                TCGEN05_WAIT_LD();
                #pragma unroll
                for (int j = 0; j < 64; j += 4) {
                    float4 bv = sbias[(nb + j) >> 2];
                    float4 o;
                    o.x = __uint_as_float(r[j + 0]) * scale + bv.x;
                    o.y = __uint_as_float(r[j + 1]) * scale + bv.y;
                    o.z = __uint_as_float(r[j + 2]) * scale + bv.z;
                    o.w = __uint_as_float(r[j + 3]) * scale + bv.w;
                    *reinterpret_cast<float4*>(orow + nb + j) = o;
                }
            }
            TCGEN05_FENCE_BEFORE();
            asm volatile("bar.sync 1, 128;" ::: "memory");
            if (tid == 0) MBARRIER_ARRIVE_LEADER(sb + SMEM_ACCF0);

            // ---- drain buf1 (cols 256..511) ----
            #pragma unroll 1
            for (int nb = 256; nb < 512; nb += 64) {
                uint32_t r[64];
                TCGEN05_LD_32X32B_X32(r, tmem + nb);
                TCGEN05_LD_32X32B_X32(r + 32, tmem + nb + 32);
                TCGEN05_WAIT_LD();
                #pragma unroll
                for (int j = 0; j < 64; j += 4) {
                    float4 bv = sbias[(nb + j) >> 2];
                    float4 o;
                    o.x = __uint_as_float(r[j + 0]) * scale + bv.x;
                    o.y = __uint_as_float(r[j + 1]) * scale + bv.y;
                    o.z = __uint_as_float(r[j + 2]) * scale + bv.z;
                    o.w = __uint_as_float(r[j + 3]) * scale + bv.w;
                    *reinterpret_cast<float4*>(orow + nb + j) = o;
                }
            }
            TCGEN05_FENCE_BEFORE();
            asm volatile("bar.sync 1, 128;" ::: "memory");
            if (tid == 0) MBARRIER_ARRIVE_LEADER(sb + SMEM_ACCF1);
        }
    }

    __syncthreads();
    if (wid == 4) {
        TCGEN05_RELINQUISH_ALLOC_PERMIT_CG2();
        TCGEN05_DEALLOC_CG2(tmem, 512);
    }
    CLUSTER_SYNC();
#else
    // ------------------------------------------------------------------
    // Fallback for PTX passes without tcgen05 (plain compute_103).
    // ------------------------------------------------------------------
    int cid  = blockIdx.x >> 1;
    int rank = blockIdx.x & 1;
    float*   lut   = reinterpret_cast<float*>(smem);
    uint8_t* wtile = reinterpret_cast<uint8_t*>(smem + 1024);
    uint8_t* atile = reinterpret_cast<uint8_t*>(smem + 1024 + 64 * KC);

    for (int i = tid; i < 256; i += 256) {
        __half_raw hr = __nv_cvt_fp8_to_halfraw((__nv_fp8_storage_t)i, __NV_E4M3);
        lut[i] = __half2float(*reinterpret_cast<__half*>(&hr));
    }
    __syncthreads();

    float scale = __ldg(s_in) * __ldg(s_w);

    for (int t = cid; t < NTILES; t += NCLUSTERS) {
        int m0, n0; tile_coords(t, m0, n0);
        int row = m0 + rank * 128 + (tid & 127);
        int half = tid >> 7;

        for (int cb = half * (TN / 128); cb < (half + 1) * (TN / 128); cb++) {
            int nb = n0 + cb * 64;
            float acc[64];
            #pragma unroll
            for (int j = 0; j < 64; j++) acc[j] = 0.0f;

            for (int c = 0; c < NCHUNK; c++) {
                __syncthreads();
                for (int idx = tid; idx < 64 * (KC / 4); idx += 256) {
                    int r = idx / (KC / 4), j = idx % (KC / 4);
                    reinterpret_cast<uint32_t*>(wtile)[idx] =
                        reinterpret_cast<const uint32_t*>(g_Wq + (size_t)(nb + r) * K_TOT + c * KC)[j];
                }
                if (half == 0) {
                    for (int j = 0; j < KC / 4; j++) {
                        reinterpret_cast<uint32_t*>(atile)[(tid & 127) * (KC / 4) + j] =
                            reinterpret_cast<const uint32_t*>(g_Aq + (size_t)row * K_TOT + c * KC)[j];
                    }
                }
                __syncthreads();

                for (int n = 0; n < 64; n++) {
                    float s = 0.0f;
                    const uint32_t* wr = reinterpret_cast<const uint32_t*>(wtile + n * KC);
                    const uint32_t* ar = reinterpret_cast<const uint32_t*>(atile + (tid & 127) * KC);
                    for (int k4 = 0; k4 < KC / 4; k4++) {
                        uint32_t av = ar[k4], wv = wr[k4];
                        s += lut[av & 0xFF]         * lut[wv & 0xFF];
                        s += lut[(av >> 8) & 0xFF]  * lut[(wv >> 8) & 0xFF];
                        s += lut[(av >> 16) & 0xFF] * lut[(wv >> 16) & 0xFF];
                        s += lut[(av >> 24) & 0xFF] * lut[(wv >> 24) & 0xFF];
                    }
                    acc[n] += s;
                }
            }

            float* orow = out + (size_t)row * N_TOT + nb;
            for (int n = 0; n < 64; n++)
                orow[n] = acc[n] * scale + __ldg(bias + nb + n);
            __syncthreads();
        }
    }
#endif
}

// ============================================================================
// Host launch
// ============================================================================

typedef CUresult (*cuTensorMapEncodeTiled_t)(
    CUtensorMap*, CUtensorMapDataType, cuuint32_t, void*,
    const cuuint64_t*, const cuuint64_t*, const cuuint32_t*, const cuuint32_t*,
    CUtensorMapInterleave, CUtensorMapSwizzle, CUtensorMapL2promotion,
    CUtensorMapFloatOOBfill);

static cuTensorMapEncodeTiled_t get_encode_fn() {
    void* fn = nullptr;
    cudaDriverEntryPointQueryResult st;
#if CUDART_VERSION >= 12050
    cudaGetDriverEntryPointByVersion("cuTensorMapEncodeTiled", &fn, 12000,
                                     cudaEnableDefault, &st);
#else
    cudaGetDriverEntryPoint("cuTensorMapEncodeTiled", &fn, cudaEnableDefault, &st);
#endif
    return (cuTensorMapEncodeTiled_t)fn;
}

static void encode_fp8_map(cuTensorMapEncodeTiled_t enc, CUtensorMap* out_map,
                           void* base, uint64_t rows) {
    uint64_t dims[3]    = {(uint64_t)K_TOT, rows, 1};
    uint64_t strides[2] = {(uint64_t)K_TOT, (uint64_t)K_TOT * rows};
    uint32_t box[3]     = {(uint32_t)KC, 128, 1};
    uint32_t estr[3]    = {1, 1, 1};
    enc(out_map, CU_TENSOR_MAP_DATA_TYPE_UINT8, 3, base,
        dims, strides, box, estr,
        CU_TENSOR_MAP_INTERLEAVE_NONE, CU_TENSOR_MAP_SWIZZLE_128B,
        CU_TENSOR_MAP_L2_PROMOTION_L2_128B, CU_TENSOR_MAP_FLOAT_OOB_FILL_NONE);
}

extern "C" void kernel_launch(void* const* d_in, const int* in_sizes, int n_in,
                              void* d_out, int out_size) {
    const float* x    = (const float*)d_in[0];
    const uint8_t* w  = (const uint8_t*)d_in[1];  // fp8 weights (raw / f32 / bf16)
    const float* bias = (const float*)d_in[2];
    const float* s_in = (const float*)d_in[3];
    const float* s_w  = (const float*)d_in[4];
    float* out        = (float*)d_out;

    probe_kernel<<<1, 32>>>(w);
    wquant_kernel<<<4096, 256>>>(w);
    quant_kernel<<<2048, 256>>>(x, s_in);

    void* aq_ptr = nullptr;
    void* wq_ptr = nullptr;
    cudaGetSymbolAddress(&aq_ptr, g_Aq);
    cudaGetSymbolAddress(&wq_ptr, g_Wq);
    cuTensorMapEncodeTiled_t enc = get_encode_fn();
    CUtensorMap tma_a, tma_b;
    encode_fp8_map(enc, &tma_a, aq_ptr, (uint64_t)M_TOT);
    encode_fp8_map(enc, &tma_b, wq_ptr, (uint64_t)N_TOT);

    cudaFuncSetAttribute(fp8gemm_kernel,
                         cudaFuncAttributeMaxDynamicSharedMemorySize, SMEM_TOTAL);
    fp8gemm_kernel<<<NSM, 256, SMEM_TOTAL>>>(
        tma_a, tma_b, bias, s_in, s_w, out);
}

// round 7
// speedup vs baseline: 1.3092x; 1.0076x over previous
#include <cuda_runtime.h>
#include <cuda.h>
#include <cuda_fp8.h>
#include <cuda_fp16.h>
#include <cuda_bf16.h>
#include <cstdint>
#include <cstdio>

// ============================================================================
// Arch-feature gate (see R1 post-mortem).
// ============================================================================
#if defined(__CUDA_ARCH__) && \
    (defined(__CUDA_ARCH_FEAT_SM103_ALL) || defined(__CUDA_ARCH_FEAT_SM100_ALL) || \
     defined(__CUDA_ARCH_SPECIFIC__) || defined(__CUDA_ARCH_FAMILY_SPECIFIC__))
#define HAS_TCGEN05 1
#else
#define HAS_TCGEN05 0
#endif

// ============================================================================
// Helpers
// ============================================================================

__device__ __forceinline__ uint32_t elect_one_pred() {
    uint32_t pred;
    asm volatile(
        "{\n\t"
        ".reg .pred p;\n\t"
        "elect.sync _|p, 0xFFFFFFFF;\n\t"
        "selp.b32 %0, 1, 0, p;\n\t"
        "}"
        : "=r"(pred));
    return pred;
}

__device__ __forceinline__ uint32_t smem_to_u32(const void* smem_ptr) {
    uint32_t addr;
    asm("{ .reg .u64 tmp; cvta.to.shared.u64 tmp, %1; cvt.u32.u64 %0, tmp; }"
        : "=r"(addr) : "l"(smem_ptr));
    return addr;
}

__device__ __forceinline__ uint32_t cluster_ctarank_u32() {
    uint32_t r;
    asm("mov.u32 %0, %%cluster_ctarank;" : "=r"(r));
    return r;
}

#define MBARRIER_INIT(mbar, count) \
    asm volatile("mbarrier.init.shared.b64 [%0], %1;" \
                 :: "r"((uint32_t)(mbar)), "r"((uint32_t)(count)) : "memory")

#define MBARRIER_EXPECT_TX(mbar, tx_bytes) \
    asm volatile("mbarrier.arrive.expect_tx.shared.b64 _, [%0], %1;" \
                 :: "r"((uint32_t)(mbar)), "r"((uint32_t)(tx_bytes)) : "memory")

// Arrive on the leader CTA's copy of this barrier (clear bit 24).
#define MBARRIER_ARRIVE_LEADER(mbar) \
    asm volatile( \
        "{\n\t" \
        ".reg .b32 la;\n\t" \
        "and.b32 la, %0, 0xFEFFFFFF;\n\t" \
        "mbarrier.arrive.shared::cluster.b64 _, [la];\n\t" \
        "}" \
        :: "r"((uint32_t)(mbar)) : "memory")

#define MBARRIER_WAIT_PARITY(mbar, parity) do {                                  \
    uint32_t _mbar = (uint32_t)(mbar);                                           \
    uint32_t _par  = (uint32_t)(parity);                                         \
    asm volatile(                                                                \
        "{\n\t"                                                                  \
        ".reg .pred P1;\n\t"                                                     \
        "WAIT_LOOP_%=:\n\t"                                                      \
        "mbarrier.try_wait.parity.acquire.cta.shared::cta.b64 P1, [%0], %1, 0x989680;\n\t" \
        "@P1 bra.uni WAIT_DONE_%=;\n\t"                                          \
        "bra.uni WAIT_LOOP_%=;\n\t"                                              \
        "WAIT_DONE_%=:\n\t"                                                      \
        "}"                                                                      \
        :: "r"(_mbar), "r"(_par) : "memory");                                    \
} while (0)

#define MBARRIER_WAIT_PARITY_RELAXED(mbar, parity) do {                          \
    uint32_t _mbar = (uint32_t)(mbar);                                           \
    uint32_t _par  = (uint32_t)(parity);                                         \
    asm volatile(                                                                \
        "{\n\t"                                                                  \
        ".reg .pred P1;\n\t"                                                     \
        "WAIT_LOOP_%=:\n\t"                                                      \
        "mbarrier.try_wait.parity.relaxed.cta.shared::cta.b64 P1, [%0], %1, 0x989680;\n\t" \
        "@P1 bra.uni WAIT_DONE_%=;\n\t"                                          \
        "bra.uni WAIT_LOOP_%=;\n\t"                                              \
        "WAIT_DONE_%=:\n\t"                                                      \
        "}"                                                                      \
        :: "r"(_mbar), "r"(_par) : "memory");                                    \
} while (0)

// Plain per-CTA TMA load (shared::cta dest, local mbarrier). This is the
// fast inbound path (R3 sustained 40+ B/cyc/SM); the cg2 cluster variant
// measured only ~27 B/cyc/SM sustained (R5/R6 post-mortems).
#define TMA_LOAD_3D(smem_addr, tensor_map, cx, cy, cz, mbar) \
    asm volatile( \
        "cp.async.bulk.tensor.3d.shared::cta.global.tile.mbarrier::complete_tx::bytes " \
        "[%0], [%1, {%2, %3, %4}], [%5];" \
        :: "r"((uint32_t)(smem_addr)), "l"(tensor_map), \
           "r"((int32_t)(cx)), "r"((int32_t)(cy)), "r"((int32_t)(cz)), \
           "r"((uint32_t)(mbar)) \
        : "memory")

#define TCGEN05_ALLOC_CG2(smem_result_addr, nCols) \
    asm volatile("tcgen05.alloc.cta_group::2.sync.aligned.shared::cta.b32 [%0], %1;" \
                 :: "r"((uint32_t)(smem_result_addr)), "r"((uint32_t)(nCols)) : "memory")

#define TCGEN05_DEALLOC_CG2(tmem_addr, nCols) \
    asm volatile("tcgen05.dealloc.cta_group::2.sync.aligned.b32 %0, %1;" \
                 :: "r"(tmem_addr), "r"((uint32_t)(nCols)))

#define TCGEN05_RELINQUISH_ALLOC_PERMIT_CG2() \
    asm volatile("tcgen05.relinquish_alloc_permit.cta_group::2.sync.aligned;")

#define TCGEN05_COMMIT_MULTICAST_CG2(mbar, cta_mask) \
    asm volatile( \
        "tcgen05.commit.cta_group::2.mbarrier::arrive::one.shared::cluster.multicast::cluster.b64 [%0], %1;" \
        :: "r"((uint32_t)(mbar)), "h"((uint16_t)(cta_mask)) : "memory")

#define TCGEN05_FENCE_AFTER() \
    asm volatile("tcgen05.fence::after_thread_sync;" ::: "memory")

#define TCGEN05_FENCE_BEFORE() \
    asm volatile("tcgen05.fence::before_thread_sync;" ::: "memory")

#define TCGEN05_WAIT_LD() \
    asm volatile("tcgen05.wait::ld.sync.aligned;" ::: "memory")

#define CLUSTER_SYNC() do { \
    asm volatile("barrier.cluster.arrive.aligned;" ::: "memory"); \
    asm volatile("barrier.cluster.wait.aligned;" ::: "memory"); \
} while (0)

#define TCGEN05_LD_32X32B_X32(r, tmem_addr) \
    asm volatile( \
        "tcgen05.ld.sync.aligned.32x32b.x32.b32 " \
        "{%0, %1, %2, %3, %4, %5, %6, %7, " \
        " %8, %9, %10, %11, %12, %13, %14, %15, " \
        " %16, %17, %18, %19, %20, %21, %22, %23, " \
        " %24, %25, %26, %27, %28, %29, %30, %31}, [%32];" \
        : "=r"((r)[0]),  "=r"((r)[1]),  "=r"((r)[2]),  "=r"((r)[3]), \
          "=r"((r)[4]),  "=r"((r)[5]),  "=r"((r)[6]),  "=r"((r)[7]), \
          "=r"((r)[8]),  "=r"((r)[9]),  "=r"((r)[10]), "=r"((r)[11]), \
          "=r"((r)[12]), "=r"((r)[13]), "=r"((r)[14]), "=r"((r)[15]), \
          "=r"((r)[16]), "=r"((r)[17]), "=r"((r)[18]), "=r"((r)[19]), \
          "=r"((r)[20]), "=r"((r)[21]), "=r"((r)[22]), "=r"((r)[23]), \
          "=r"((r)[24]), "=r"((r)[25]), "=r"((r)[26]), "=r"((r)[27]), \
          "=r"((r)[28]), "=r"((r)[29]), "=r"((r)[30]), "=r"((r)[31]) \
        : "r"(tmem_addr))

// SW128 K-major SMEM descriptor (LBO=1, SBO=64, version=1, layout=SW128)
static constexpr uint64_t SMEM_DESC_BASE_SW128 =
    (uint64_t(2)  << 61)
    | (uint64_t(1) << 46)
    | (uint64_t(64) << 32)
    | (uint64_t(1) << 16);

#define MAKE_SMEM_DESC(base_addr) \
    (SMEM_DESC_BASE_SW128 | ((uint64_t)((base_addr) >> 4) & 0x3FFF))

#if HAS_TCGEN05
__device__ __forceinline__ void tcgen05_mma_f8_ss_cg2(
    uint32_t d_tmem, uint64_t a_desc, uint64_t b_desc, uint32_t idesc, bool acc)
{
    uint32_t en = acc ? 1u : 0u;
    asm volatile(
        "{\n\t"
        ".reg .pred p;\n\t"
        "setp.ne.u32 p, %5, 0;\n\t"
        "tcgen05.mma.cta_group::2.kind::f8f6f4 [%0], %1, %2, %3, "
        "{%4, %4, %4, %4, %4, %4, %4, %4}, p;\n\t"
        "}"
        :: "r"(d_tmem), "l"(a_desc), "l"(b_desc), "r"(idesc), "r"(0u), "r"(en)
        : "memory");
}
#endif

// ============================================================================
// Problem constants
// ============================================================================

static constexpr int M_TOT = 8192;      // B*S
static constexpr int K_TOT = 4096;
static constexpr int N_TOT = 16384;

static constexpr int TMP   = 256;       // M tile per CTA pair (128 per CTA)
static constexpr int TN    = 512;       // N tile per pair (2 x N=256 cg2 MMAs)
static constexpr int MMA_N = 256;
static constexpr int KC    = 128;       // K chunk (bytes == fp8 elements)
static constexpr int NCHUNK = K_TOT / KC;   // 32
static constexpr int NSTAGES = 4;
static constexpr int RUNWAY  = NSTAGES; // chunks of MMA0-only issued before ACCF1

static constexpr int A_BYTES = 128 * KC;        // per-CTA A half
static constexpr int BSEG    = 128 * KC;        // per-CTA half of one N=256 atom
static constexpr int STAGE_BYTES = A_BYTES + 2 * BSEG;   // 49152 per CTA

// SMEM layout
static constexpr int SMEM_TMEM  = 0;
static constexpr int SMEM_DONE  = 16;   // MMA->epilogue per-tile completion
static constexpr int SMEM_ACCF0 = 24;   // epilogue->MMA: buf0 free (count=2)
static constexpr int SMEM_FULL0 = 32;   // leader full[s]=32+s*16 (count=2), empty[s]=40+s*16
static constexpr int SMEM_ACCF1 = 96;   // epilogue->MMA: buf1 free (count=2)
static constexpr int SMEM_FULLL = 112;  // local TMA-complete fullL[s] = 112+s*8
static constexpr int SMEM_BIAS  = 1024; // 512 floats (2 KB)
static constexpr int SMEM_TILE0 = 3072; // 1024-aligned tile stages
static constexpr int SMEM_TOTAL = SMEM_TILE0 + NSTAGES * STAGE_BYTES;  // 199680

static constexpr int TILES_MP = M_TOT / TMP;   // 32 m-pairs
static constexpr int TILES_NT = N_TOT / TN;    // 32 n-tiles
static constexpr int NTILES   = TILES_MP * TILES_NT;   // 1024
static constexpr int GROUP_MP = 8;             // raster grouping for L2 reuse

static constexpr int NSM       = 152;   // GB300
static constexpr int NCLUSTERS = NSM / 2;  // 76 persistent clusters

// idesc for cg2 kind::f8f6f4, e4m3 x e4m3 -> f32, M=256, N=256
static constexpr uint32_t MMA_IDESC_CG2 =
    (1u << 4) | ((uint32_t)(MMA_N / 8) << 17) | ((uint32_t)(TMP / 16) << 24);

// Scratch: quantized activations + canonical e4m3 weights
__device__ __align__(256) uint8_t g_Aq[(size_t)M_TOT * K_TOT];
__device__ __align__(256) uint8_t g_Wq[(size_t)N_TOT * K_TOT];
__device__ int g_wmode;   // 0 = raw fp8 bytes, 1 = float32 upcast, 2 = bf16 upcast

// Tile raster (shared by all roles): grouped for L2 reuse.
__device__ __forceinline__ void tile_coords(int t, int& m0, int& n0) {
    int group = t / (GROUP_MP * TILES_NT);
    int inner = t % (GROUP_MP * TILES_NT);
    int mt = group * GROUP_MP + (inner % GROUP_MP);
    int nt = inner / GROUP_MP;
    m0 = mt * TMP;
    n0 = nt * TN;
}

// ============================================================================
// Kernel 0: probe weight dtype (see R2 post-mortem).
// ============================================================================

__global__ void probe_kernel(const uint8_t* __restrict__ w)
{
    if (threadIdx.x != 0 || blockIdx.x != 0) return;
    const uint32_t* wu = reinterpret_cast<const uint32_t*>(w);
    bool is_f32 = true;
    for (int i = 0; i < 64; i++) {
        uint32_t b = wu[i];
        float v = __uint_as_float(b);
        bool ok = (fabsf(v) < 1.0f) && ((b & 0xFFFFFu) == 0u);
        if (!ok) { is_f32 = false; break; }
    }
    if (is_f32) { g_wmode = 1; return; }
    const uint16_t* wh = reinterpret_cast<const uint16_t*>(w);
    bool is_bf16 = true;
    for (int i = 0; i < 128; i++) {
        float v = __uint_as_float(((uint32_t)wh[i]) << 16);
        if (!(fabsf(v) < 1.0f)) { is_bf16 = false; break; }
    }
    g_wmode = is_bf16 ? 2 : 0;
}

// ============================================================================
// Kernel 1: materialize canonical e4m3 weight bytes in g_Wq
// ============================================================================

__global__ void __launch_bounds__(256) wquant_kernel(const uint8_t* __restrict__ w)
{
    int mode = g_wmode;
    const unsigned n16 = (unsigned)(((size_t)N_TOT * K_TOT) / 16u);
    uint4* __restrict__ ov = reinterpret_cast<uint4*>(g_Wq);
    unsigned stride = blockDim.x * gridDim.x;

    if (mode == 1) {
        const float4* __restrict__ wf = reinterpret_cast<const float4*>(w);
        for (unsigned i = blockIdx.x * blockDim.x + threadIdx.x; i < n16; i += stride) {
            unsigned r[4];
            #pragma unroll
            for (int j = 0; j < 4; j++) {
                float4 v = wf[(size_t)i * 4 + j];
                unsigned p0 = (unsigned)__nv_cvt_float2_to_fp8x2(
                    make_float2(v.x, v.y), __NV_SATFINITE, __NV_E4M3);
                unsigned p1 = (unsigned)__nv_cvt_float2_to_fp8x2(
                    make_float2(v.z, v.w), __NV_SATFINITE, __NV_E4M3);
                r[j] = p0 | (p1 << 16);
            }
            ov[i] = make_uint4(r[0], r[1], r[2], r[3]);
        }
    } else if (mode == 2) {
        const uint4* __restrict__ wb = reinterpret_cast<const uint4*>(w);
        for (unsigned i = blockIdx.x * blockDim.x + threadIdx.x; i < n16; i += stride) {
            unsigned r[4];
            #pragma unroll
            for (int half = 0; half < 2; half++) {
                uint4 v = wb[(size_t)i * 2 + half];
                unsigned u[4] = {v.x, v.y, v.z, v.w};
                #pragma unroll
                for (int j = 0; j < 2; j++) {
                    float2 f0, f1;
                    f0.x = __uint_as_float((u[j*2+0] & 0xFFFFu) << 16);
                    f0.y = __uint_as_float((u[j*2+0] >> 16) << 16);
                    f1.x = __uint_as_float((u[j*2+1] & 0xFFFFu) << 16);
                    f1.y = __uint_as_float((u[j*2+1] >> 16) << 16);
                    unsigned p0 = (unsigned)__nv_cvt_float2_to_fp8x2(f0, __NV_SATFINITE, __NV_E4M3);
                    unsigned p1 = (unsigned)__nv_cvt_float2_to_fp8x2(f1, __NV_SATFINITE, __NV_E4M3);
                    r[half*2 + j] = p0 | (p1 << 16);
                }
            }
            ov[i] = make_uint4(r[0], r[1], r[2], r[3]);
        }
    } else {
        const uint4* __restrict__ wb = reinterpret_cast<const uint4*>(w);
        for (unsigned i = blockIdx.x * blockDim.x + threadIdx.x; i < n16; i += stride) {
            ov[i] = wb[i];
        }
    }
}

// ============================================================================
// Kernel 2: quantize x (f32) -> e4m3 at x/input_scale
// ============================================================================

__global__ void __launch_bounds__(256) quant_kernel(
    const float* __restrict__ x, const float* __restrict__ s_in)
{
    float inv = 1.0f / __ldg(s_in);
    const unsigned n16 = (unsigned)(((size_t)M_TOT * K_TOT) / 16u);
    const float4* __restrict__ xv = reinterpret_cast<const float4*>(x);
    uint4* __restrict__ ov = reinterpret_cast<uint4*>(g_Aq);
    unsigned stride = blockDim.x * gridDim.x;
    for (unsigned i = blockIdx.x * blockDim.x + threadIdx.x; i < n16; i += stride) {
        unsigned r[4];
        #pragma unroll
        for (int j = 0; j < 4; j++) {
            float4 v = xv[(size_t)i * 4 + j];
            float2 lo = make_float2(v.x * inv, v.y * inv);
            float2 hi = make_float2(v.z * inv, v.w * inv);
            unsigned p0 = (unsigned)__nv_cvt_float2_to_fp8x2(lo, __NV_SATFINITE, __NV_E4M3);
            unsigned p1 = (unsigned)__nv_cvt_float2_to_fp8x2(hi, __NV_SATFINITE, __NV_E4M3);
            r[j] = p0 | (p1 << 16);
        }
        ov[i] = make_uint4(r[0], r[1], r[2], r[3]);
    }
}

// ============================================================================
// Kernel 3: persistent warp-specialized 2-CTA FP8 GEMM.
//   Loads: plain per-CTA TMA -> local fullL[s]; relay warp forwards completion
//   to the leader's full[s] (count=2). MMA: cg2 split accumulator + runway.
//   Warps: 0-3 epilogue, 4 TMA producer, 5 MMA issuer (leader), 6 relay.
// ============================================================================

__global__ void __launch_bounds__(256, 1) __cluster_dims__(2, 1, 1)
fp8gemm_kernel(const __grid_constant__ CUtensorMap tma_a,
               const __grid_constant__ CUtensorMap tma_b,
               const float* __restrict__ bias,
               const float* __restrict__ s_in,
               const float* __restrict__ s_w,
               float* __restrict__ out)
{
    extern __shared__ char smem[];
    int tid = threadIdx.x;

#if HAS_TCGEN05
    uint32_t sb = smem_to_u32(smem);
    int wid = tid >> 5;
    int lid = tid & 31;
    uint32_t rank = cluster_ctarank_u32();
    int cid = blockIdx.x >> 1;
    int nchunks_mine = ((NTILES - cid + NCLUSTERS - 1) / NCLUSTERS) * NCHUNK;

    if (wid == 4) TCGEN05_ALLOC_CG2(sb + SMEM_TMEM, 512);
    if (tid == 0) {
        MBARRIER_INIT(sb + SMEM_DONE, 1);
        MBARRIER_INIT(sb + SMEM_ACCF0, 2);
        MBARRIER_INIT(sb + SMEM_ACCF1, 2);
        #pragma unroll
        for (int s = 0; s < NSTAGES; s++) {
            MBARRIER_INIT(sb + SMEM_FULL0 + s * 16, 2);      // leader full[s]: 2 relays
            MBARRIER_INIT(sb + SMEM_FULL0 + s * 16 + 8, 1);  // empty[s] (per-CTA)
            MBARRIER_INIT(sb + SMEM_FULLL + s * 8, 1);       // local TMA fullL[s]
        }
        asm volatile("fence.mbarrier_init.release.cluster;" ::: "memory");
    }
    __syncthreads();
    CLUSTER_SYNC();

    uint32_t tmem;
    asm volatile("ld.shared.b32 %0, [%1];" : "=r"(tmem) : "r"(sb + SMEM_TMEM));

    if (wid == 4) {
        // ---- TMA producer (per-CTA, plain shared::cta loads -> local fullL) ----
        if (elect_one_pred()) {
            int stage = 0, phase = 1;
            for (int t = cid; t < NTILES; t += NCLUSTERS) {
                int m0, n0; tile_coords(t, m0, n0);
                for (int c = 0; c < NCHUNK; c++) {
                    MBARRIER_WAIT_PARITY_RELAXED(sb + SMEM_FULL0 + stage * 16 + 8, phase);
                    uint32_t lbar = sb + SMEM_FULLL + stage * 8;
                    MBARRIER_EXPECT_TX(lbar, STAGE_BYTES);
                    uint32_t dst = sb + SMEM_TILE0 + stage * STAGE_BYTES;
                    TMA_LOAD_3D(dst, &tma_a, c * KC, m0 + (int)rank * 128, 0, lbar);
                    TMA_LOAD_3D(dst + A_BYTES, &tma_b,
                                c * KC, n0 + (int)rank * 128, 0, lbar);
                    TMA_LOAD_3D(dst + A_BYTES + BSEG, &tma_b,
                                c * KC, n0 + 256 + (int)rank * 128, 0, lbar);
                    if (++stage == NSTAGES) { stage = 0; phase ^= 1; }
                }
            }
        }
    } else if (wid == 6) {
        // ---- Relay: local TMA completion -> leader full[s] (cluster arrive) ----
        if (elect_one_pred()) {
            int stage = 0, phase = 0;
            for (int i = 0; i < nchunks_mine; i++) {
                MBARRIER_WAIT_PARITY_RELAXED(sb + SMEM_FULLL + stage * 8, phase);
                MBARRIER_ARRIVE_LEADER(sb + SMEM_FULL0 + stage * 16);
                if (++stage == NSTAGES) { stage = 0; phase ^= 1; }
            }
        }
    } else if (wid == 5 && rank == 0) {
        // ---- MMA issuer (leader only), runway-scheduled split accumulator ----
        if (elect_one_pred()) {
            int stage = 0, phase = 0;
            int ph0 = 1, ph1 = 1;       // fresh-barrier convention
            int held[RUNWAY];
            for (int t = cid; t < NTILES; t += NCLUSTERS) {
                MBARRIER_WAIT_PARITY(sb + SMEM_ACCF0, ph0);
                ph0 ^= 1;
                TCGEN05_FENCE_AFTER();
                for (int c = 0; c < NCHUNK; c++) {
                    MBARRIER_WAIT_PARITY_RELAXED(sb + SMEM_FULL0 + stage * 16, phase);
                    uint32_t base = sb + SMEM_TILE0 + stage * STAGE_BYTES;
                    uint64_t ad  = MAKE_SMEM_DESC(base);
                    uint64_t bd0 = MAKE_SMEM_DESC(base + A_BYTES);
                    #pragma unroll
                    for (int k = 0; k < KC / 32; k++)
                        tcgen05_mma_f8_ss_cg2(tmem, ad + k * 2, bd0 + k * 2,
                                              MMA_IDESC_CG2, !(c == 0 && k == 0));
                    if (c < RUNWAY) {
                        held[c] = stage;            // defer MMA1 + stage release
                    } else {
                        uint64_t bd1 = MAKE_SMEM_DESC(base + A_BYTES + BSEG);
                        #pragma unroll
                        for (int k = 0; k < KC / 32; k++)
                            tcgen05_mma_f8_ss_cg2(tmem + 256, ad + k * 2, bd1 + k * 2,
                                                  MMA_IDESC_CG2, true);
                        TCGEN05_COMMIT_MULTICAST_CG2(sb + SMEM_FULL0 + stage * 16 + 8, 0x3);
                    }
                    if (c == RUNWAY - 1) {
                        // buf1 must be free before its first write this tile
                        MBARRIER_WAIT_PARITY(sb + SMEM_ACCF1, ph1);
                        ph1 ^= 1;
                        TCGEN05_FENCE_AFTER();
                        #pragma unroll
                        for (int r = 0; r < RUNWAY; r++) {
                            uint32_t hb = sb + SMEM_TILE0 + held[r] * STAGE_BYTES;
                            uint64_t had = MAKE_SMEM_DESC(hb);
                            uint64_t hbd = MAKE_SMEM_DESC(hb + A_BYTES + BSEG);
                            #pragma unroll
                            for (int k = 0; k < KC / 32; k++)
                                tcgen05_mma_f8_ss_cg2(tmem + 256, had + k * 2, hbd + k * 2,
                                                      MMA_IDESC_CG2, !(r == 0 && k == 0));
                            TCGEN05_COMMIT_MULTICAST_CG2(sb + SMEM_FULL0 + held[r] * 16 + 8, 0x3);
                        }
                    }
                    if (++stage == NSTAGES) { stage = 0; phase ^= 1; }
                }
                TCGEN05_COMMIT_MULTICAST_CG2(sb + SMEM_DONE, 0x3);
            }
        }
    } else if (wid < 4) {
        // ---- Epilogue (warps 0-3 of both CTAs) ----
        float scale = __ldg(s_in) * __ldg(s_w);
        int row = wid * 32 + lid;                  // 0..127 (M within CTA half)
        int doneph = 0;
        float4* sbias = reinterpret_cast<float4*>(smem + SMEM_BIAS);
        for (int t = cid; t < NTILES; t += NCLUSTERS) {
            int m0, n0; tile_coords(t, m0, n0);
            // Preload bias for this tile (overlaps with the MMA phase)
            sbias[tid] = *reinterpret_cast<const float4*>(bias + n0 + tid * 4);
            asm volatile("bar.sync 1, 128;" ::: "memory");

            MBARRIER_WAIT_PARITY(sb + SMEM_DONE, doneph);
            doneph ^= 1;
            TCGEN05_FENCE_AFTER();

            float* orow = out + (size_t)(m0 + (int)rank * 128 + row) * N_TOT + n0;
            // ---- drain buf0 (cols 0..255) ----
            #pragma unroll 1
            for (int nb = 0; nb < 256; nb += 64) {
                uint32_t r[64];
                TCGEN05_LD_32X32B_X32(r, tmem + nb);
                TCGEN05_LD_32X32B_X32(r + 32, tmem + nb + 32);
                TCGEN05_WAIT_LD();
                #pragma unroll
                for (int j = 0; j < 64; j += 4) {
                    float4 bv = sbias[(nb + j) >> 2];
                    float4 o;
                    o.x = __uint_as_float(r[j + 0]) * scale + bv.x;
                    o.y = __uint_as_float(r[j + 1]) * scale + bv.y;
                    o.z = __uint_as_float(r[j + 2]) * scale + bv.z;
                    o.w = __uint_as_float(r[j + 3]) * scale + bv.w;
                    *reinterpret_cast<float4*>(orow + nb + j) = o;
                }
            }
            TCGEN05_FENCE_BEFORE();
            asm volatile("bar.sync 1, 128;" ::: "memory");
            if (tid == 0) MBARRIER_ARRIVE_LEADER(sb + SMEM_ACCF0);

            // ---- drain buf1 (cols 256..511) ----
            #pragma unroll 1
            for (int nb = 256; nb < 512; nb += 64) {
                uint32_t r[64];
                TCGEN05_LD_32X32B_X32(r, tmem + nb);
                TCGEN05_LD_32X32B_X32(r + 32, tmem + nb + 32);
                TCGEN05_WAIT_LD();
                #pragma unroll
                for (int j = 0; j < 64; j += 4) {
                    float4 bv = sbias[(nb + j) >> 2];
                    float4 o;
                    o.x = __uint_as_float(r[j + 0]) * scale + bv.x;
                    o.y = __uint_as_float(r[j + 1]) * scale + bv.y;
                    o.z = __uint_as_float(r[j + 2]) * scale + bv.z;
                    o.w = __uint_as_float(r[j + 3]) * scale + bv.w;
                    *reinterpret_cast<float4*>(orow + nb + j) = o;
                }
            }
            TCGEN05_FENCE_BEFORE();
            asm volatile("bar.sync 1, 128;" ::: "memory");
            if (tid == 0) MBARRIER_ARRIVE_LEADER(sb + SMEM_ACCF1);
        }
    }

    __syncthreads();
    if (wid == 4) {
        TCGEN05_RELINQUISH_ALLOC_PERMIT_CG2();
        TCGEN05_DEALLOC_CG2(tmem, 512);
    }
    CLUSTER_SYNC();
#else
    // ------------------------------------------------------------------
    // Fallback for PTX passes without tcgen05 (plain compute_103).
    // ------------------------------------------------------------------
    int cid  = blockIdx.x >> 1;
    int rank = blockIdx.x & 1;
    float*   lut   = reinterpret_cast<float*>(smem);
    uint8_t* wtile = reinterpret_cast<uint8_t*>(smem + 1024);
    uint8_t* atile = reinterpret_cast<uint8_t*>(smem + 1024 + 64 * KC);

    for (int i = tid; i < 256; i += 256) {
        __half_raw hr = __nv_cvt_fp8_to_halfraw((__nv_fp8_storage_t)i, __NV_E4M3);
        lut[i] = __half2float(*reinterpret_cast<__half*>(&hr));
    }
    __syncthreads();

    float scale = __ldg(s_in) * __ldg(s_w);

    for (int t = cid; t < NTILES; t += NCLUSTERS) {
        int m0, n0; tile_coords(t, m0, n0);
        int row = m0 + rank * 128 + (tid & 127);
        int half = tid >> 7;

        for (int cb = half * (TN / 128); cb < (half + 1) * (TN / 128); cb++) {
            int nb = n0 + cb * 64;
            float acc[64];
            #pragma unroll
            for (int j = 0; j < 64; j++) acc[j] = 0.0f;

            for (int c = 0; c < NCHUNK; c++) {
                __syncthreads();
                for (int idx = tid; idx < 64 * (KC / 4); idx += 256) {
                    int r = idx / (KC / 4), j = idx % (KC / 4);
                    reinterpret_cast<uint32_t*>(wtile)[idx] =
                        reinterpret_cast<const uint32_t*>(g_Wq + (size_t)(nb + r) * K_TOT + c * KC)[j];
                }
                if (half == 0) {
                    for (int j = 0; j < KC / 4; j++) {
                        reinterpret_cast<uint32_t*>(atile)[(tid & 127) * (KC / 4) + j] =
                            reinterpret_cast<const uint32_t*>(g_Aq + (size_t)row * K_TOT + c * KC)[j];
                    }
                }
                __syncthreads();

                for (int n = 0; n < 64; n++) {
                    float s = 0.0f;
                    const uint32_t* wr = reinterpret_cast<const uint32_t*>(wtile + n * KC);
                    const uint32_t* ar = reinterpret_cast<const uint32_t*>(atile + (tid & 127) * KC);
                    for (int k4 = 0; k4 < KC / 4; k4++) {
                        uint32_t av = ar[k4], wv = wr[k4];
                        s += lut[av & 0xFF]         * lut[wv & 0xFF];
                        s += lut[(av >> 8) & 0xFF]  * lut[(wv >> 8) & 0xFF];
                        s += lut[(av >> 16) & 0xFF] * lut[(wv >> 16) & 0xFF];
                        s += lut[(av >> 24) & 0xFF] * lut[(wv >> 24) & 0xFF];
                    }
                    acc[n] += s;
                }
            }

            float* orow = out + (size_t)row * N_TOT + nb;
            for (int n = 0; n < 64; n++)
                orow[n] = acc[n] * scale + __ldg(bias + nb + n);
            __syncthreads();
        }
    }
#endif
}

// ============================================================================
// Host launch
// ============================================================================

typedef CUresult (*cuTensorMapEncodeTiled_t)(
    CUtensorMap*, CUtensorMapDataType, cuuint32_t, void*,
    const cuuint64_t*, const cuuint64_t*, const cuuint32_t*, const cuuint32_t*,
    CUtensorMapInterleave, CUtensorMapSwizzle, CUtensorMapL2promotion,
    CUtensorMapFloatOOBfill);

static cuTensorMapEncodeTiled_t get_encode_fn() {
    void* fn = nullptr;
    cudaDriverEntryPointQueryResult st;
#if CUDART_VERSION >= 12050
    cudaGetDriverEntryPointByVersion("cuTensorMapEncodeTiled", &fn, 12000,
                                     cudaEnableDefault, &st);
#else
    cudaGetDriverEntryPoint("cuTensorMapEncodeTiled", &fn, cudaEnableDefault, &st);
#endif
    return (cuTensorMapEncodeTiled_t)fn;
}

static void encode_fp8_map(cuTensorMapEncodeTiled_t enc, CUtensorMap* out_map,
                           void* base, uint64_t rows) {
    uint64_t dims[3]    = {(uint64_t)K_TOT, rows, 1};
    uint64_t strides[2] = {(uint64_t)K_TOT, (uint64_t)K_TOT * rows};
    uint32_t box[3]     = {(uint32_t)KC, 128, 1};
    uint32_t estr[3]    = {1, 1, 1};
    enc(out_map, CU_TENSOR_MAP_DATA_TYPE_UINT8, 3, base,
        dims, strides, box, estr,
        CU_TENSOR_MAP_INTERLEAVE_NONE, CU_TENSOR_MAP_SWIZZLE_128B,
        CU_TENSOR_MAP_L2_PROMOTION_L2_128B, CU_TENSOR_MAP_FLOAT_OOB_FILL_NONE);
}

extern "C" void kernel_launch(void* const* d_in, const int* in_sizes, int n_in,
                              void* d_out, int out_size) {
    const float* x    = (const float*)d_in[0];
    const uint8_t* w  = (const uint8_t*)d_in[1];  // fp8 weights (raw / f32 / bf16)
    const float* bias = (const float*)d_in[2];
    const float* s_in = (const float*)d_in[3];
    const float* s_w  = (const float*)d_in[4];
    float* out        = (float*)d_out;

    probe_kernel<<<1, 32>>>(w);
    wquant_kernel<<<4096, 256>>>(w);
    quant_kernel<<<2048, 256>>>(x, s_in);

    void* aq_ptr = nullptr;
    void* wq_ptr = nullptr;
    cudaGetSymbolAddress(&aq_ptr, g_Aq);
    cudaGetSymbolAddress(&wq_ptr, g_Wq);
    cuTensorMapEncodeTiled_t enc = get_encode_fn();
    CUtensorMap tma_a, tma_b;
    encode_fp8_map(enc, &tma_a, aq_ptr, (uint64_t)M_TOT);
    encode_fp8_map(enc, &tma_b, wq_ptr, (uint64_t)N_TOT);

    cudaFuncSetAttribute(fp8gemm_kernel,
                         cudaFuncAttributeMaxDynamicSharedMemorySize, SMEM_TOTAL);
    fp8gemm_kernel<<<NSM, 256, SMEM_TOTAL>>>(
        tma_a, tma_b, bias, s_in, s_w, out);
}